// round 1
// baseline (speedup 1.0000x reference)
#include <cuda_runtime.h>
#include <math.h>

#define Tn 4
#define Bn 4
#define Cn 64
#define Ln 4096
#define NLAYERS 10
#define TL 64          // l-tile per block
#define GS_STRIDE 68   // padded row stride for gated smem

// ---------------- scratch (no allocations allowed) ----------------
__device__ float g_xA[Tn*Bn*Cn*Ln];     // 16 MB
__device__ float g_xB[Tn*Bn*Cn*Ln];     // 16 MB
__device__ float g_skip[Tn*Bn*Cn*Ln];   // 16 MB
__device__ float g_proj[Bn*Cn];

// ---------------- packed f32x2 helpers ----------------
__device__ __forceinline__ unsigned long long pk2(float w){
    unsigned long long r;
    asm("mov.b64 %0, {%1, %1};" : "=l"(r) : "f"(w));
    return r;
}
__device__ __forceinline__ void f2fma(unsigned long long &d, unsigned long long a, unsigned long long b){
    asm("fma.rn.f32x2 %0, %1, %2, %0;" : "+l"(d) : "l"(a), "l"(b));
}
__device__ __forceinline__ float lo32(unsigned long long v){ return __uint_as_float((unsigned)v); }
__device__ __forceinline__ float hi32(unsigned long long v){ return __uint_as_float((unsigned)(v>>32)); }

// ---------------- JAX threefry2x32 (key = (0,42)) ----------------
__device__ __forceinline__ unsigned rotl32(unsigned x, int r){ return (x<<r)|(x>>(32-r)); }

__device__ __forceinline__ void threefry_0_42(unsigned x0, unsigned x1, unsigned &o0, unsigned &o1){
    const unsigned ks0 = 0u, ks1 = 42u, ks2 = 0u ^ 42u ^ 0x1BD11BDAu;
    x0 += ks0; x1 += ks1;
#define TF_RND(r) { x0 += x1; x1 = rotl32(x1,(r)); x1 ^= x0; }
    TF_RND(13) TF_RND(15) TF_RND(26) TF_RND(6)
    x0 += ks1; x1 += ks2 + 1u;
    TF_RND(17) TF_RND(29) TF_RND(16) TF_RND(24)
    x0 += ks2; x1 += ks0 + 2u;
    TF_RND(13) TF_RND(15) TF_RND(26) TF_RND(6)
    x0 += ks0; x1 += ks1 + 3u;
    TF_RND(17) TF_RND(29) TF_RND(16) TF_RND(24)
    x0 += ks1; x1 += ks2 + 4u;
    TF_RND(13) TF_RND(15) TF_RND(26) TF_RND(6)
    x0 += ks2; x1 += ks0 + 5u;
#undef TF_RND
    o0 = x0; o1 = x1;
}
__device__ __forceinline__ float bits2unit(unsigned b){
    return __uint_as_float((b >> 9) | 0x3f800000u) - 1.0f;
}

// ---------------- encoder: poisson + input conv(1x1) + LIF; zero skip ----------------
__global__ void __launch_bounds__(256) enc_kernel(const float* __restrict__ audio,
                                                  const float* __restrict__ w_in,
                                                  const float* __restrict__ b_in){
    int g = blockIdx.x * 256 + threadIdx.x;      // 0..16383  (b,l)
    int b = g >> 12, l = g & (Ln - 1);
    float a = audio[g];

    // bits index n = (t*B + b)*L + l ; iota split: bits[i]=out0(i, i+32768) for i<32768
    unsigned n0 = (unsigned)(b * Ln + l);        // t=0; partner t=2
    unsigned o0, o1, o2, o3;
    threefry_0_42(n0,           n0 + 32768u, o0, o2);
    threefry_0_42(n0 + 16384u,  n0 + 49152u, o1, o3);   // t=1 ; partner t=3

    float sp[4];
    sp[0] = (bits2unit(o0) < a) ? 1.f : 0.f;
    sp[1] = (bits2unit(o1) < a) ? 1.f : 0.f;
    sp[2] = (bits2unit(o2) < a) ? 1.f : 0.f;
    sp[3] = (bits2unit(o3) < a) ? 1.f : 0.f;

    for (int c = 0; c < Cn; c++){
        float w = w_in[c], bi = b_in[c];
        float v = 0.f;
#pragma unroll
        for (int t = 0; t < Tn; t++){
            float x = w * sp[t] + bi;
            v = v + __fdiv_rn(x - v, 1.2f);
            float s = (v >= 0.5f) ? 1.f : 0.f;
            v *= (1.f - s);
            int idx = ((t*Bn + b)*Cn + c)*Ln + l;
            g_xA[idx]   = s;
            g_skip[idx] = 0.f;
        }
    }
}

// ---------------- per-layer diffusion-step embedding + projection ----------------
__global__ void __launch_bounds__(256) proj_kernel(const int* __restrict__ dstep,
                                                   const float* __restrict__ w1,
                                                   const float* __restrict__ b1,
                                                   const float* __restrict__ w2,
                                                   const float* __restrict__ b2,
                                                   const float* __restrict__ dpw,
                                                   const float* __restrict__ dpb){
    __shared__ float h[Bn][Cn];
    __shared__ float e[Bn][Cn];
    int tid = threadIdx.x;
    int b = tid >> 6, c = tid & 63;

    float d = (float)dstep[b];
    float z = d * w1[c] + b1[c];
    float sg = 1.f / (1.f + expf(-z));
    h[b][c] = z * sg;                     // silu
    __syncthreads();

    float acc = b2[c];
    for (int j = 0; j < Cn; j++) acc += h[b][j] * w2[c*Cn + j];
    e[b][c] = acc;
    __syncthreads();

    float p = dpb[c];
    for (int j = 0; j < Cn; j++) p += e[b][j] * dpw[c*Cn + j];
    g_proj[b*Cn + c] = p;
}

// ---------------- fused layer: dilated conv + LIF + gate + skip/res 1x1 ----------------
// block = (l-tile of 64, batch b); 256 threads: pair = tid>>2 (cout pair c,c+64), lg = tid&3
__global__ void __launch_bounds__(256, 1) layer_kernel(int flip,
                                                       const float* __restrict__ wconv,
                                                       const float* __restrict__ bconv,
                                                       const float* __restrict__ wskip,
                                                       const float* __restrict__ bskip,
                                                       const float* __restrict__ wres,
                                                       const float* __restrict__ bres,
                                                       int dil){
    const float* x_in  = flip ? g_xB : g_xA;
    float*       x_out = flip ? g_xA : g_xB;

    extern __shared__ float sm[];
    float* wc   = sm;            // [(k*64+cin)*128 + cout]  24576
    float* wsk  = wc   + 24576;  // [cin*64 + cout]          4096
    float* wrs  = wsk  + 4096;   //                          4096
    float* cb   = wrs  + 4096;   // 128
    float* pr   = cb   + 128;    // 64
    float* sbv  = pr   + 64;     // 64
    float* rbv  = sbv  + 64;     // 64
    float* tile = rbv  + 64;     // 3 shifts x [64][64]      12288
    float* gsm  = tile + 12288;  // [64][GS_STRIDE]          4352

    const int tid  = threadIdx.x;
    const int b    = blockIdx.y;
    const int l0   = blockIdx.x * TL;
    const int lg   = tid & 3;
    const int pair = tid >> 2;
    const int lbase = lg * 16;

    // cooperative weight load + repack
    for (int i = tid; i < 24576; i += 256){
        int co = i / 192, r = i % 192, ci = r / 3, k = r % 3;
        wc[(k*64 + ci)*128 + co] = wconv[i];
    }
    for (int i = tid; i < 4096; i += 256){
        int co = i >> 6, ci = i & 63;
        wsk[ci*64 + co] = wskip[i];
        wrs[ci*64 + co] = wres[i];
    }
    if (tid < 128) cb[tid] = bconv[tid];
    if (tid < 64){
        pr[tid]  = g_proj[b*Cn + tid];
        sbv[tid] = bskip[tid];
        rbv[tid] = bres[tid];
    }
    __syncthreads();

    const float SG1 = 1.f / (1.f + expf(-1.f));
    const float TH1 = tanhf(1.f);

    float v0[16], v1[16];
#pragma unroll
    for (int k = 0; k < 16; k++){ v0[k] = 0.f; v1[k] = 0.f; }

    for (int t = 0; t < Tn; t++){
        // ---- stage (x + proj) with zero padding, 3 shifted tiles ----
        const float* xin_t = x_in + ((size_t)(t*Bn + b)) * Cn * Ln;
        for (int i = tid; i < 3*Cn*TL; i += 256){
            int s = i / (Cn*TL); int r = i % (Cn*TL);
            int ci = r >> 6;     int j = r & 63;
            int gl = l0 + j + (s - 1) * dil;
            float val = 0.f;
            if (gl >= 0 && gl < Ln) val = xin_t[ci*Ln + gl] + pr[ci];
            tile[s*(Cn*TL) + ci*TL + j] = val;
        }
        __syncthreads();

        // ---- dilated conv, 2 couts x 16 l per thread, packed f32x2 ----
        unsigned long long acc0[8], acc1[8];
        {
            unsigned long long c0 = pk2(cb[pair]);
            unsigned long long c1 = pk2(cb[pair + 64]);
#pragma unroll
            for (int q = 0; q < 8; q++){ acc0[q] = c0; acc1[q] = c1; }
        }
#pragma unroll 1
        for (int ci = 0; ci < Cn; ci++){
            const float* wrow = wc + ci*128;
            unsigned long long wA0 = pk2(wrow[pair]);
            unsigned long long wA1 = pk2(wrow[8192  + pair]);
            unsigned long long wA2 = pk2(wrow[16384 + pair]);
            unsigned long long wB0 = pk2(wrow[64 + pair]);
            unsigned long long wB1 = pk2(wrow[8192  + 64 + pair]);
            unsigned long long wB2 = pk2(wrow[16384 + 64 + pair]);
            const ulonglong2* xm = (const ulonglong2*)(tile +         ci*TL + lbase);
            const ulonglong2* xz = (const ulonglong2*)(tile + 4096 +  ci*TL + lbase);
            const ulonglong2* xp = (const ulonglong2*)(tile + 8192 +  ci*TL + lbase);
#pragma unroll
            for (int q = 0; q < 4; q++){
                ulonglong2 a = xm[q], z = xz[q], p = xp[q];
                f2fma(acc0[2*q  ], wA0, a.x); f2fma(acc0[2*q+1], wA0, a.y);
                f2fma(acc0[2*q  ], wA1, z.x); f2fma(acc0[2*q+1], wA1, z.y);
                f2fma(acc0[2*q  ], wA2, p.x); f2fma(acc0[2*q+1], wA2, p.y);
                f2fma(acc1[2*q  ], wB0, a.x); f2fma(acc1[2*q+1], wB0, a.y);
                f2fma(acc1[2*q  ], wB1, z.x); f2fma(acc1[2*q+1], wB1, z.y);
                f2fma(acc1[2*q  ], wB2, p.x); f2fma(acc1[2*q+1], wB2, p.y);
            }
        }

        // ---- LIF (hard reset) + gating sigmoid(gate)*tanh(filt) on 0/1 spikes ----
        float gbuf[16];
#pragma unroll
        for (int q = 0; q < 8; q++){
            float a0[2] = { lo32(acc0[q]), hi32(acc0[q]) };
            float a1[2] = { lo32(acc1[q]), hi32(acc1[q]) };
#pragma unroll
            for (int h = 0; h < 2; h++){
                int k = 2*q + h;
                v0[k] = v0[k] + __fdiv_rn(a0[h] - v0[k], 1.2f);
                float s0 = (v0[k] >= 0.5f) ? 1.f : 0.f;
                v0[k] *= (1.f - s0);
                v1[k] = v1[k] + __fdiv_rn(a1[h] - v1[k], 1.2f);
                float s1 = (v1[k] >= 0.5f) ? 1.f : 0.f;
                v1[k] *= (1.f - s1);
                float sg = (s0 > 0.f) ? SG1 : 0.5f;
                float th = (s1 > 0.f) ? TH1 : 0.f;
                gbuf[k] = sg * th;
            }
        }
        {
            float* grow = gsm + pair*GS_STRIDE + lbase;
#pragma unroll
            for (int q = 0; q < 4; q++){
                float4 v4 = make_float4(gbuf[4*q], gbuf[4*q+1], gbuf[4*q+2], gbuf[4*q+3]);
                *(float4*)(grow + 4*q) = v4;
            }
        }
        __syncthreads();

        // ---- skip / res 1x1 convs over gated activations (in smem) ----
        unsigned long long skp[8], rsp[8];
#pragma unroll
        for (int q = 0; q < 8; q++){ skp[q] = 0ull; rsp[q] = 0ull; }
#pragma unroll 1
        for (int ci = 0; ci < Cn; ci++){
            unsigned long long ws = pk2(wsk[ci*64 + pair]);
            unsigned long long wr = pk2(wrs[ci*64 + pair]);
            const ulonglong2* gp = (const ulonglong2*)(gsm + ci*GS_STRIDE + lbase);
#pragma unroll
            for (int q = 0; q < 4; q++){
                ulonglong2 gq = gp[q];
                f2fma(skp[2*q  ], ws, gq.x); f2fma(skp[2*q+1], ws, gq.y);
                f2fma(rsp[2*q  ], wr, gq.x); f2fma(rsp[2*q+1], wr, gq.y);
            }
        }

        // ---- global update: skip += conv_skip + b ; x_new = x + conv_res + b ----
        {
            size_t gofs = ((size_t)(t*Bn + b)*Cn + pair)*Ln + l0 + lbase;
            float sbp = sbv[pair], rbp = rbv[pair];
#pragma unroll
            for (int q = 0; q < 8; q++){
                g_skip[gofs + 2*q    ] += lo32(skp[q]) + sbp;
                g_skip[gofs + 2*q + 1] += hi32(skp[q]) + sbp;
                x_out[gofs + 2*q    ] = x_in[gofs + 2*q    ] + (lo32(rsp[q]) + rbp);
                x_out[gofs + 2*q + 1] = x_in[gofs + 2*q + 1] + (hi32(rsp[q]) + rbp);
            }
        }
        __syncthreads();   // tiles & gsm reused next t
    }
}

// ---------------- final: relu(skip) -> 1x1 conv -> LIF -> sum over T ----------------
__global__ void __launch_bounds__(256) out_kernel(const float* __restrict__ wout,
                                                  const float* __restrict__ bout,
                                                  float* __restrict__ out){
    int g = blockIdx.x * 256 + threadIdx.x;     // (b,l)
    int b = g >> 12, l = g & (Ln - 1);
    float bo = bout[0];
    float v = 0.f, ssum = 0.f;
#pragma unroll
    for (int t = 0; t < Tn; t++){
        float acc = bo;
        const float* sk = g_skip + ((size_t)(t*Bn + b))*Cn*Ln + l;
        for (int c = 0; c < Cn; c++){
            float s = sk[(size_t)c*Ln];
            s = (s > 0.f) ? s : 0.f;
            acc += wout[c] * s;
        }
        v = v + __fdiv_rn(acc - v, 1.2f);
        float sp = (v >= 0.5f) ? 1.f : 0.f;
        v *= (1.f - sp);
        ssum += sp;
    }
    out[g] = ssum;
}

// ---------------- launch ----------------
extern "C" void kernel_launch(void* const* d_in, const int* in_sizes, int n_in,
                              void* d_out, int out_size){
    const float* audio   = (const float*)d_in[0];
    const int*   dstep   = (const int*)  d_in[1];
    const float* W_in    = (const float*)d_in[2];
    const float* b_in    = (const float*)d_in[3];
    const float* demb_w1 = (const float*)d_in[4];
    const float* demb_b1 = (const float*)d_in[5];
    const float* demb_w2 = (const float*)d_in[6];
    const float* demb_b2 = (const float*)d_in[7];
    const float* dproj_w = (const float*)d_in[8];
    const float* dproj_b = (const float*)d_in[9];
    const float* conv_w  = (const float*)d_in[10];
    const float* conv_b  = (const float*)d_in[11];
    const float* skip_w  = (const float*)d_in[12];
    const float* skip_b  = (const float*)d_in[13];
    const float* res_w   = (const float*)d_in[14];
    const float* res_b   = (const float*)d_in[15];
    const float* W_out   = (const float*)d_in[16];
    const float* b_out   = (const float*)d_in[17];

    const int SMEM_BYTES = 49728 * 4;   // 198912
    cudaFuncSetAttribute((const void*)layer_kernel,
                         cudaFuncAttributeMaxDynamicSharedMemorySize, SMEM_BYTES);

    enc_kernel<<<(Bn*Ln)/256, 256>>>(audio, W_in, b_in);

    int flip = 0;
    for (int i = 0; i < NLAYERS; i++){
        proj_kernel<<<1, 256>>>(dstep,
                                demb_w1 + i*Cn, demb_b1 + i*Cn,
                                demb_w2 + i*Cn*Cn, demb_b2 + i*Cn,
                                dproj_w + i*Cn*Cn, dproj_b + i*Cn);
        layer_kernel<<<dim3(Ln/TL, Bn), 256, SMEM_BYTES>>>(flip,
                                conv_w + i*2*Cn*Cn*3, conv_b + i*2*Cn,
                                skip_w + i*Cn*Cn,     skip_b + i*Cn,
                                res_w  + i*Cn*Cn,     res_b  + i*Cn,
                                1 << i);
        flip ^= 1;
    }

    out_kernel<<<(Bn*Ln)/256, 256>>>(W_out, b_out, (float*)d_out);
}

// round 2
// speedup vs baseline: 1.1994x; 1.1994x over previous
#include <cuda_runtime.h>
#include <math.h>

#define Tn 4
#define Bn 4
#define Cn 64
#define Ln 4096
#define NLAYERS 10
#define TL 64          // l-tile per block
#define GS_STRIDE 68   // padded row stride for gated smem
#define NTHREADS 512

// ---------------- scratch (no allocations allowed) ----------------
__device__ float g_xA[Tn*Bn*Cn*Ln];     // 16 MB
__device__ float g_xB[Tn*Bn*Cn*Ln];     // 16 MB
__device__ float g_skip[Tn*Bn*Cn*Ln];   // 16 MB
__device__ float g_proj[NLAYERS*Bn*Cn];

// ---------------- packed f32x2 helpers ----------------
__device__ __forceinline__ unsigned long long pk2(float w){
    unsigned long long r;
    asm("mov.b64 %0, {%1, %1};" : "=l"(r) : "f"(w));
    return r;
}
__device__ __forceinline__ void f2fma(unsigned long long &d, unsigned long long a, unsigned long long b){
    asm("fma.rn.f32x2 %0, %1, %2, %0;" : "+l"(d) : "l"(a), "l"(b));
}
__device__ __forceinline__ float lo32(unsigned long long v){ return __uint_as_float((unsigned)v); }
__device__ __forceinline__ float hi32(unsigned long long v){ return __uint_as_float((unsigned)(v>>32)); }

// ---------------- JAX threefry2x32 (key = (0,42)) ----------------
__device__ __forceinline__ unsigned rotl32(unsigned x, int r){ return (x<<r)|(x>>(32-r)); }

__device__ __forceinline__ void threefry_0_42(unsigned x0, unsigned x1, unsigned &o0, unsigned &o1){
    const unsigned ks0 = 0u, ks1 = 42u, ks2 = 0u ^ 42u ^ 0x1BD11BDAu;
    x0 += ks0; x1 += ks1;
#define TF_RND(r) { x0 += x1; x1 = rotl32(x1,(r)); x1 ^= x0; }
    TF_RND(13) TF_RND(15) TF_RND(26) TF_RND(6)
    x0 += ks1; x1 += ks2 + 1u;
    TF_RND(17) TF_RND(29) TF_RND(16) TF_RND(24)
    x0 += ks2; x1 += ks0 + 2u;
    TF_RND(13) TF_RND(15) TF_RND(26) TF_RND(6)
    x0 += ks0; x1 += ks1 + 3u;
    TF_RND(17) TF_RND(29) TF_RND(16) TF_RND(24)
    x0 += ks1; x1 += ks2 + 4u;
    TF_RND(13) TF_RND(15) TF_RND(26) TF_RND(6)
    x0 += ks2; x1 += ks0 + 5u;
#undef TF_RND
    o0 = x0; o1 = x1;
}
__device__ __forceinline__ float bits2unit(unsigned b){
    return __uint_as_float((b >> 9) | 0x3f800000u) - 1.0f;
}

// ---------------- encoder: poisson + input conv(1x1) + LIF ----------------
__global__ void __launch_bounds__(256) enc_kernel(const float* __restrict__ audio,
                                                  const float* __restrict__ w_in,
                                                  const float* __restrict__ b_in){
    int g = blockIdx.x * 256 + threadIdx.x;      // 0..16383  (b,l)
    int b = g >> 12, l = g & (Ln - 1);
    float a = audio[g];

    unsigned n0 = (unsigned)(b * Ln + l);        // t=0; partner t=2
    unsigned o0, o1, o2, o3;
    threefry_0_42(n0,           n0 + 32768u, o0, o2);
    threefry_0_42(n0 + 16384u,  n0 + 49152u, o1, o3);   // t=1 ; partner t=3

    float sp[4];
    sp[0] = (bits2unit(o0) < a) ? 1.f : 0.f;
    sp[1] = (bits2unit(o1) < a) ? 1.f : 0.f;
    sp[2] = (bits2unit(o2) < a) ? 1.f : 0.f;
    sp[3] = (bits2unit(o3) < a) ? 1.f : 0.f;

    for (int c = 0; c < Cn; c++){
        float w = w_in[c], bi = b_in[c];
        float v = 0.f;
#pragma unroll
        for (int t = 0; t < Tn; t++){
            float x = w * sp[t] + bi;
            v = v + __fdiv_rn(x - v, 1.2f);
            float s = (v >= 0.5f) ? 1.f : 0.f;
            v *= (1.f - s);
            int idx = ((t*Bn + b)*Cn + c)*Ln + l;
            g_xA[idx] = s;
        }
    }
}

// ---------------- ALL layers' diffusion-step embedding + projection ----------------
__global__ void __launch_bounds__(256) proj_all_kernel(const int* __restrict__ dstep,
                                                       const float* __restrict__ w1a,
                                                       const float* __restrict__ b1a,
                                                       const float* __restrict__ w2a,
                                                       const float* __restrict__ b2a,
                                                       const float* __restrict__ dpwa,
                                                       const float* __restrict__ dpba){
    int i = blockIdx.x;   // layer
    const float* w1 = w1a + i*Cn;
    const float* b1 = b1a + i*Cn;
    const float* w2 = w2a + i*Cn*Cn;
    const float* b2 = b2a + i*Cn;
    const float* dpw = dpwa + i*Cn*Cn;
    const float* dpb = dpba + i*Cn;

    __shared__ float h[Bn][Cn];
    __shared__ float e[Bn][Cn];
    int tid = threadIdx.x;
    int b = tid >> 6, c = tid & 63;

    float d = (float)dstep[b];
    float z = d * w1[c] + b1[c];
    float sg = 1.f / (1.f + expf(-z));
    h[b][c] = z * sg;                     // silu
    __syncthreads();

    float acc = b2[c];
    for (int j = 0; j < Cn; j++) acc += h[b][j] * w2[c*Cn + j];
    e[b][c] = acc;
    __syncthreads();

    float p = dpb[c];
    for (int j = 0; j < Cn; j++) p += e[b][j] * dpw[c*Cn + j];
    g_proj[i*Bn*Cn + b*Cn + c] = p;
}

// ---------------- fused layer: dilated conv + LIF + gate + skip/res 1x1 ----------------
// 512 threads: pair = tid>>3 (cout pair c,c+64), lg = tid&7 -> 8 l per thread
__global__ void __launch_bounds__(NTHREADS, 1) layer_kernel(int flip, int layer,
                                                       const float* __restrict__ wconv,
                                                       const float* __restrict__ bconv,
                                                       const float* __restrict__ wskip,
                                                       const float* __restrict__ bskip,
                                                       const float* __restrict__ wres,
                                                       const float* __restrict__ bres,
                                                       int dil){
    const float* x_in  = flip ? g_xB : g_xA;
    float*       x_out = flip ? g_xA : g_xB;

    extern __shared__ float sm[];
    float* wc   = sm;            // [(k*64+cin)*128 + cout]  24576
    float* wsk  = wc   + 24576;  // [cin*64 + cout]          4096
    float* wrs  = wsk  + 4096;   //                          4096
    float* cb   = wrs  + 4096;   // 128
    float* pr   = cb   + 128;    // 64
    float* sbv  = pr   + 64;     // 64
    float* rbv  = sbv  + 64;     // 64
    float* tile = rbv  + 64;     // 3 shifts x [64][64]      12288
    float* gsm  = tile + 12288;  // [64][GS_STRIDE]          4352

    const int tid  = threadIdx.x;
    const int b    = blockIdx.y;
    const int l0   = blockIdx.x * TL;
    const int lg   = tid & 7;
    const int pair = tid >> 3;
    const int lbase = lg * 8;

    // cooperative weight load + repack
    for (int i = tid; i < 24576; i += NTHREADS){
        int co = i / 192, r = i % 192, ci = r / 3, k = r % 3;
        wc[(k*64 + ci)*128 + co] = wconv[i];
    }
    for (int i = tid; i < 4096; i += NTHREADS){
        int co = i >> 6, ci = i & 63;
        wsk[ci*64 + co] = wskip[i];
        wrs[ci*64 + co] = wres[i];
    }
    if (tid < 128) cb[tid] = bconv[tid];
    if (tid < 64){
        pr[tid]  = g_proj[layer*Bn*Cn + b*Cn + tid];
        sbv[tid] = bskip[tid];
        rbv[tid] = bres[tid];
    }
    __syncthreads();

    const float SG1 = 1.f / (1.f + expf(-1.f));
    const float TH1 = tanhf(1.f);

    float v0[8], v1[8];
#pragma unroll
    for (int k = 0; k < 8; k++){ v0[k] = 0.f; v1[k] = 0.f; }

    for (int t = 0; t < Tn; t++){
        // ---- stage (x + proj) with zero padding, 3 shifted tiles ----
        const float* xin_t = x_in + ((size_t)(t*Bn + b)) * Cn * Ln;
#pragma unroll
        for (int i = tid; i < 3*Cn*TL; i += NTHREADS){
            int s = i / (Cn*TL); int r = i % (Cn*TL);
            int ci = r >> 6;     int j = r & 63;
            int gl = l0 + j + (s - 1) * dil;
            float val = 0.f;
            if ((unsigned)gl < (unsigned)Ln) val = xin_t[ci*Ln + gl] + pr[ci];
            tile[s*(Cn*TL) + ci*TL + j] = val;
        }
        __syncthreads();

        // ---- dilated conv, 2 couts x 8 l per thread, packed f32x2 ----
        unsigned long long acc0[4], acc1[4];
        {
            unsigned long long c0 = pk2(cb[pair]);
            unsigned long long c1 = pk2(cb[pair + 64]);
#pragma unroll
            for (int q = 0; q < 4; q++){ acc0[q] = c0; acc1[q] = c1; }
        }
#pragma unroll 4
        for (int ci = 0; ci < Cn; ci++){
            const float* wrow = wc + ci*128;
            unsigned long long wA0 = pk2(wrow[pair]);
            unsigned long long wA1 = pk2(wrow[8192  + pair]);
            unsigned long long wA2 = pk2(wrow[16384 + pair]);
            unsigned long long wB0 = pk2(wrow[64 + pair]);
            unsigned long long wB1 = pk2(wrow[8192  + 64 + pair]);
            unsigned long long wB2 = pk2(wrow[16384 + 64 + pair]);
            const ulonglong2* xm = (const ulonglong2*)(tile +         ci*TL + lbase);
            const ulonglong2* xz = (const ulonglong2*)(tile + 4096 +  ci*TL + lbase);
            const ulonglong2* xp = (const ulonglong2*)(tile + 8192 +  ci*TL + lbase);
#pragma unroll
            for (int q = 0; q < 2; q++){
                ulonglong2 a = xm[q], z = xz[q], p = xp[q];
                f2fma(acc0[2*q  ], wA0, a.x); f2fma(acc0[2*q+1], wA0, a.y);
                f2fma(acc0[2*q  ], wA1, z.x); f2fma(acc0[2*q+1], wA1, z.y);
                f2fma(acc0[2*q  ], wA2, p.x); f2fma(acc0[2*q+1], wA2, p.y);
                f2fma(acc1[2*q  ], wB0, a.x); f2fma(acc1[2*q+1], wB0, a.y);
                f2fma(acc1[2*q  ], wB1, z.x); f2fma(acc1[2*q+1], wB1, z.y);
                f2fma(acc1[2*q  ], wB2, p.x); f2fma(acc1[2*q+1], wB2, p.y);
            }
        }

        // ---- LIF (hard reset) + gating sigmoid(gate)*tanh(filt) on 0/1 spikes ----
        float gbuf[8];
#pragma unroll
        for (int q = 0; q < 4; q++){
            float a0[2] = { lo32(acc0[q]), hi32(acc0[q]) };
            float a1[2] = { lo32(acc1[q]), hi32(acc1[q]) };
#pragma unroll
            for (int h = 0; h < 2; h++){
                int k = 2*q + h;
                v0[k] = v0[k] + __fdiv_rn(a0[h] - v0[k], 1.2f);
                float s0 = (v0[k] >= 0.5f) ? 1.f : 0.f;
                v0[k] *= (1.f - s0);
                v1[k] = v1[k] + __fdiv_rn(a1[h] - v1[k], 1.2f);
                float s1 = (v1[k] >= 0.5f) ? 1.f : 0.f;
                v1[k] *= (1.f - s1);
                float sg = (s0 > 0.f) ? SG1 : 0.5f;
                float th = (s1 > 0.f) ? TH1 : 0.f;
                gbuf[k] = sg * th;
            }
        }
        {
            float* grow = gsm + pair*GS_STRIDE + lbase;
            *(float4*)(grow    ) = make_float4(gbuf[0], gbuf[1], gbuf[2], gbuf[3]);
            *(float4*)(grow + 4) = make_float4(gbuf[4], gbuf[5], gbuf[6], gbuf[7]);
        }
        __syncthreads();

        // ---- skip / res 1x1 convs over gated activations (in smem) ----
        unsigned long long skp[4], rsp[4];
#pragma unroll
        for (int q = 0; q < 4; q++){ skp[q] = 0ull; rsp[q] = 0ull; }
#pragma unroll 4
        for (int ci = 0; ci < Cn; ci++){
            unsigned long long ws = pk2(wsk[ci*64 + pair]);
            unsigned long long wr = pk2(wrs[ci*64 + pair]);
            const ulonglong2* gp = (const ulonglong2*)(gsm + ci*GS_STRIDE + lbase);
#pragma unroll
            for (int q = 0; q < 2; q++){
                ulonglong2 gq = gp[q];
                f2fma(skp[2*q  ], ws, gq.x); f2fma(skp[2*q+1], ws, gq.y);
                f2fma(rsp[2*q  ], wr, gq.x); f2fma(rsp[2*q+1], wr, gq.y);
            }
        }

        // ---- global update: skip += conv_skip + b ; x_new = x + conv_res + b ----
        {
            size_t gofs = ((size_t)(t*Bn + b)*Cn + pair)*Ln + l0 + lbase;
            float sbp = sbv[pair], rbp = rbv[pair];
            float4 sv0 = make_float4(lo32(skp[0])+sbp, hi32(skp[0])+sbp,
                                     lo32(skp[1])+sbp, hi32(skp[1])+sbp);
            float4 sv1 = make_float4(lo32(skp[2])+sbp, hi32(skp[2])+sbp,
                                     lo32(skp[3])+sbp, hi32(skp[3])+sbp);
            float4* skx = (float4*)(g_skip + gofs);
            if (layer != 0){
                float4 o0 = skx[0], o1 = skx[1];
                sv0.x += o0.x; sv0.y += o0.y; sv0.z += o0.z; sv0.w += o0.w;
                sv1.x += o1.x; sv1.y += o1.y; sv1.z += o1.z; sv1.w += o1.w;
            }
            skx[0] = sv0; skx[1] = sv1;

            const float4* xi = (const float4*)(x_in + gofs);
            float4* xo = (float4*)(x_out + gofs);
            float4 a0 = xi[0], a1 = xi[1];
            a0.x += lo32(rsp[0])+rbp; a0.y += hi32(rsp[0])+rbp;
            a0.z += lo32(rsp[1])+rbp; a0.w += hi32(rsp[1])+rbp;
            a1.x += lo32(rsp[2])+rbp; a1.y += hi32(rsp[2])+rbp;
            a1.z += lo32(rsp[3])+rbp; a1.w += hi32(rsp[3])+rbp;
            xo[0] = a0; xo[1] = a1;
        }
        __syncthreads();   // gsm/tile reuse barrier for next t
    }
}

// ---------------- final: relu(skip) -> 1x1 conv -> LIF -> sum over T ----------------
__global__ void __launch_bounds__(256) out_kernel(const float* __restrict__ wout,
                                                  const float* __restrict__ bout,
                                                  float* __restrict__ out){
    int g = blockIdx.x * 256 + threadIdx.x;     // (b,l)
    int b = g >> 12, l = g & (Ln - 1);
    float bo = bout[0];
    float v = 0.f, ssum = 0.f;
#pragma unroll
    for (int t = 0; t < Tn; t++){
        float acc = bo;
        const float* sk = g_skip + ((size_t)(t*Bn + b))*Cn*Ln + l;
        for (int c = 0; c < Cn; c++){
            float s = sk[(size_t)c*Ln];
            s = (s > 0.f) ? s : 0.f;
            acc += wout[c] * s;
        }
        v = v + __fdiv_rn(acc - v, 1.2f);
        float sp = (v >= 0.5f) ? 1.f : 0.f;
        v *= (1.f - sp);
        ssum += sp;
    }
    out[g] = ssum;
}

// ---------------- launch ----------------
extern "C" void kernel_launch(void* const* d_in, const int* in_sizes, int n_in,
                              void* d_out, int out_size){
    const float* audio   = (const float*)d_in[0];
    const int*   dstep   = (const int*)  d_in[1];
    const float* W_in    = (const float*)d_in[2];
    const float* b_in    = (const float*)d_in[3];
    const float* demb_w1 = (const float*)d_in[4];
    const float* demb_b1 = (const float*)d_in[5];
    const float* demb_w2 = (const float*)d_in[6];
    const float* demb_b2 = (const float*)d_in[7];
    const float* dproj_w = (const float*)d_in[8];
    const float* dproj_b = (const float*)d_in[9];
    const float* conv_w  = (const float*)d_in[10];
    const float* conv_b  = (const float*)d_in[11];
    const float* skip_w  = (const float*)d_in[12];
    const float* skip_b  = (const float*)d_in[13];
    const float* res_w   = (const float*)d_in[14];
    const float* res_b   = (const float*)d_in[15];
    const float* W_out   = (const float*)d_in[16];
    const float* b_out   = (const float*)d_in[17];

    const int SMEM_BYTES = 49728 * 4;   // 198912
    cudaFuncSetAttribute((const void*)layer_kernel,
                         cudaFuncAttributeMaxDynamicSharedMemorySize, SMEM_BYTES);

    enc_kernel<<<(Bn*Ln)/256, 256>>>(audio, W_in, b_in);

    proj_all_kernel<<<NLAYERS, 256>>>(dstep, demb_w1, demb_b1, demb_w2, demb_b2,
                                      dproj_w, dproj_b);

    int flip = 0;
    for (int i = 0; i < NLAYERS; i++){
        layer_kernel<<<dim3(Ln/TL, Bn), NTHREADS, SMEM_BYTES>>>(flip, i,
                                conv_w + i*2*Cn*Cn*3, conv_b + i*2*Cn,
                                skip_w + i*Cn*Cn,     skip_b + i*Cn,
                                res_w  + i*Cn*Cn,     res_b  + i*Cn,
                                1 << i);
        flip ^= 1;
    }

    out_kernel<<<(Bn*Ln)/256, 256>>>(W_out, b_out, (float*)d_out);
}

// round 3
// speedup vs baseline: 2.2056x; 1.8389x over previous
#include <cuda_runtime.h>
#include <math.h>

#define Tn 4
#define Bn 4
#define Cn 64
#define Ln 4096
#define NLAYERS 10
#define TL 64          // l-tile per block
#define GS_STRIDE 68   // padded row stride for gated smem
#define NTHREADS 512

// ---------------- scratch (no allocations allowed) ----------------
__device__ float g_xA[Tn*Bn*Cn*Ln];     // 16 MB
__device__ float g_xB[Tn*Bn*Cn*Ln];     // 16 MB
__device__ float g_skip[Tn*Bn*Cn*Ln];   // 16 MB
__device__ float g_proj[NLAYERS*Bn*Cn];

// ---------------- packed f32x2 helpers ----------------
__device__ __forceinline__ unsigned long long pk2(float w){
    unsigned long long r;
    asm("mov.b64 %0, {%1, %1};" : "=l"(r) : "f"(w));
    return r;
}
__device__ __forceinline__ void f2fma(unsigned long long &d, unsigned long long a, unsigned long long b){
    asm("fma.rn.f32x2 %0, %1, %2, %0;" : "+l"(d) : "l"(a), "l"(b));
}
__device__ __forceinline__ float lo32(unsigned long long v){ return __uint_as_float((unsigned)v); }
__device__ __forceinline__ float hi32(unsigned long long v){ return __uint_as_float((unsigned)(v>>32)); }

// ---------------- JAX threefry2x32 (key = (0,42)) ----------------
__device__ __forceinline__ unsigned rotl32(unsigned x, int r){ return (x<<r)|(x>>(32-r)); }

__device__ __forceinline__ void threefry_0_42(unsigned x0, unsigned x1, unsigned &o0, unsigned &o1){
    const unsigned ks0 = 0u, ks1 = 42u, ks2 = 0u ^ 42u ^ 0x1BD11BDAu;
    x0 += ks0; x1 += ks1;
#define TF_RND(r) { x0 += x1; x1 = rotl32(x1,(r)); x1 ^= x0; }
    TF_RND(13) TF_RND(15) TF_RND(26) TF_RND(6)
    x0 += ks1; x1 += ks2 + 1u;
    TF_RND(17) TF_RND(29) TF_RND(16) TF_RND(24)
    x0 += ks2; x1 += ks0 + 2u;
    TF_RND(13) TF_RND(15) TF_RND(26) TF_RND(6)
    x0 += ks0; x1 += ks1 + 3u;
    TF_RND(17) TF_RND(29) TF_RND(16) TF_RND(24)
    x0 += ks1; x1 += ks2 + 4u;
    TF_RND(13) TF_RND(15) TF_RND(26) TF_RND(6)
    x0 += ks2; x1 += ks0 + 5u;
#undef TF_RND
    o0 = x0; o1 = x1;
}
__device__ __forceinline__ float bits2unit(unsigned b){
    return __uint_as_float((b >> 9) | 0x3f800000u) - 1.0f;
}

// ---------------- encoder: poisson + input conv(1x1) + LIF ----------------
__global__ void __launch_bounds__(256) enc_kernel(const float* __restrict__ audio,
                                                  const float* __restrict__ w_in,
                                                  const float* __restrict__ b_in){
    int g = blockIdx.x * 256 + threadIdx.x;      // 0..16383  (b,l)
    int b = g >> 12, l = g & (Ln - 1);
    float a = audio[g];

    unsigned n0 = (unsigned)(b * Ln + l);        // t=0; partner t=2
    unsigned o0, o1, o2, o3;
    threefry_0_42(n0,           n0 + 32768u, o0, o2);
    threefry_0_42(n0 + 16384u,  n0 + 49152u, o1, o3);   // t=1 ; partner t=3

    float sp[4];
    sp[0] = (bits2unit(o0) < a) ? 1.f : 0.f;
    sp[1] = (bits2unit(o1) < a) ? 1.f : 0.f;
    sp[2] = (bits2unit(o2) < a) ? 1.f : 0.f;
    sp[3] = (bits2unit(o3) < a) ? 1.f : 0.f;

    for (int c = 0; c < Cn; c++){
        float w = w_in[c], bi = b_in[c];
        float v = 0.f;
#pragma unroll
        for (int t = 0; t < Tn; t++){
            float x = w * sp[t] + bi;
            v = v + __fdiv_rn(x - v, 1.2f);
            float s = (v >= 0.5f) ? 1.f : 0.f;
            v *= (1.f - s);
            int idx = ((t*Bn + b)*Cn + c)*Ln + l;
            g_xA[idx] = s;
        }
    }
}

// ---------------- ALL layers' diffusion-step embedding + projection ----------------
__global__ void __launch_bounds__(256) proj_all_kernel(const int* __restrict__ dstep,
                                                       const float* __restrict__ w1a,
                                                       const float* __restrict__ b1a,
                                                       const float* __restrict__ w2a,
                                                       const float* __restrict__ b2a,
                                                       const float* __restrict__ dpwa,
                                                       const float* __restrict__ dpba){
    int i = blockIdx.x;   // layer
    const float* w1 = w1a + i*Cn;
    const float* b1 = b1a + i*Cn;
    const float* w2 = w2a + i*Cn*Cn;
    const float* b2 = b2a + i*Cn;
    const float* dpw = dpwa + i*Cn*Cn;
    const float* dpb = dpba + i*Cn;

    __shared__ float h[Bn][Cn];
    __shared__ float e[Bn][Cn];
    int tid = threadIdx.x;
    int b = tid >> 6, c = tid & 63;

    float d = (float)dstep[b];
    float z = d * w1[c] + b1[c];
    float sg = 1.f / (1.f + expf(-z));
    h[b][c] = z * sg;                     // silu
    __syncthreads();

    float acc = b2[c];
    for (int j = 0; j < Cn; j++) acc += h[b][j] * w2[c*Cn + j];
    e[b][c] = acc;
    __syncthreads();

    float p = dpb[c];
    for (int j = 0; j < Cn; j++) p += e[b][j] * dpw[c*Cn + j];
    g_proj[i*Bn*Cn + b*Cn + c] = p;
}

// ---------------- fused layer: dilated conv + LIF + gate + skip/res 1x1 ----------------
// 512 threads: pair = tid>>3 (cout pair c,c+64), lg = tid&7
// thread owns l chunks {lg*4..+3} and {32+lg*4..+3}  (bank-spread, conflict-free)
__global__ void __launch_bounds__(NTHREADS, 1) layer_kernel(int flip, int layer,
                                                       const float* __restrict__ wconv,
                                                       const float* __restrict__ bconv,
                                                       const float* __restrict__ wskip,
                                                       const float* __restrict__ bskip,
                                                       const float* __restrict__ wres,
                                                       const float* __restrict__ bres,
                                                       int dil){
    const float* x_in  = flip ? g_xB : g_xA;
    float*       x_out = flip ? g_xA : g_xB;

    extern __shared__ float sm[];
    float* wc3  = sm;            // [ci][128 cout][k0,k1,k2,pad]   32768
    float* wskr = wc3  + 32768;  // [ci][64 cout][{ws,wr}]          8192
    float* cb   = wskr + 8192;   // 128
    float* pr   = cb   + 128;    // 64
    float* sbv  = pr   + 64;     // 64
    float* rbv  = sbv  + 64;     // 64
    float* tile = rbv  + 64;     // 3 shifts x [64][64]            12288
    float* gsm  = tile + 12288;  // [64][GS_STRIDE]                 4352
                                 // total = 57920 floats = 231680 B

    const int tid  = threadIdx.x;
    const int b    = blockIdx.y;
    const int l0   = blockIdx.x * TL;
    const int lg   = tid & 7;
    const int pair = tid >> 3;
    const int jA   = lg * 4;
    const int jB   = 32 + lg * 4;

    // cooperative weight load + repack
    for (int i = tid; i < 24576; i += NTHREADS){
        int co = i / 192, r = i % 192, ci = r / 3, k = r % 3;
        wc3[((ci << 7) + co)*4 + k] = wconv[i];
    }
    for (int i = tid; i < 4096; i += NTHREADS){
        int co = i >> 6, ci = i & 63;
        wskr[((ci << 6) + co)*2 + 0] = wskip[i];
        wskr[((ci << 6) + co)*2 + 1] = wres[i];
    }
    if (tid < 128) cb[tid] = bconv[tid];
    if (tid < 64){
        pr[tid]  = g_proj[layer*Bn*Cn + b*Cn + tid];
        sbv[tid] = bskip[tid];
        rbv[tid] = bres[tid];
    }
    __syncthreads();

    const float SG1 = 1.f / (1.f + expf(-1.f));
    const float TH1 = tanhf(1.f);

    float v0[8], v1[8];
#pragma unroll
    for (int k = 0; k < 8; k++){ v0[k] = 0.f; v1[k] = 0.f; }

    for (int t = 0; t < Tn; t++){
        // ---- stage (x + proj) with zero padding, 3 shifted tiles ----
        const float* xin_t = x_in + ((size_t)(t*Bn + b)) * Cn * Ln;
#pragma unroll
        for (int i = tid; i < 3*Cn*TL; i += NTHREADS){
            int s = i / (Cn*TL); int r = i % (Cn*TL);
            int ci = r >> 6;     int j = r & 63;
            int gl = l0 + j + (s - 1) * dil;
            float val = 0.f;
            if ((unsigned)gl < (unsigned)Ln) val = xin_t[ci*Ln + gl] + pr[ci];
            tile[s*(Cn*TL) + (ci << 6) + j] = val;
        }
        __syncthreads();

        // ---- dilated conv, 2 couts x 8 l per thread, packed f32x2 ----
        unsigned long long acc0[4], acc1[4];
        {
            unsigned long long c0 = pk2(cb[pair]);
            unsigned long long c1 = pk2(cb[pair + 64]);
#pragma unroll
            for (int q = 0; q < 4; q++){ acc0[q] = c0; acc1[q] = c1; }
        }
#pragma unroll 4
        for (int ci = 0; ci < Cn; ci++){
            float4 wAv = *(const float4*)(wc3 + (((ci << 7) + pair) << 2));
            float4 wBv = *(const float4*)(wc3 + (((ci << 7) + 64 + pair) << 2));
            unsigned long long wA0 = pk2(wAv.x), wA1 = pk2(wAv.y), wA2 = pk2(wAv.z);
            unsigned long long wB0 = pk2(wBv.x), wB1 = pk2(wBv.y), wB2 = pk2(wBv.z);
            const float* trow = tile + (ci << 6);
            {
                ulonglong2 a = *(const ulonglong2*)(trow + jA);
                ulonglong2 z = *(const ulonglong2*)(trow + 4096 + jA);
                ulonglong2 p = *(const ulonglong2*)(trow + 8192 + jA);
                f2fma(acc0[0], wA0, a.x); f2fma(acc0[1], wA0, a.y);
                f2fma(acc0[0], wA1, z.x); f2fma(acc0[1], wA1, z.y);
                f2fma(acc0[0], wA2, p.x); f2fma(acc0[1], wA2, p.y);
                f2fma(acc1[0], wB0, a.x); f2fma(acc1[1], wB0, a.y);
                f2fma(acc1[0], wB1, z.x); f2fma(acc1[1], wB1, z.y);
                f2fma(acc1[0], wB2, p.x); f2fma(acc1[1], wB2, p.y);
            }
            {
                ulonglong2 a = *(const ulonglong2*)(trow + jB);
                ulonglong2 z = *(const ulonglong2*)(trow + 4096 + jB);
                ulonglong2 p = *(const ulonglong2*)(trow + 8192 + jB);
                f2fma(acc0[2], wA0, a.x); f2fma(acc0[3], wA0, a.y);
                f2fma(acc0[2], wA1, z.x); f2fma(acc0[3], wA1, z.y);
                f2fma(acc0[2], wA2, p.x); f2fma(acc0[3], wA2, p.y);
                f2fma(acc1[2], wB0, a.x); f2fma(acc1[3], wB0, a.y);
                f2fma(acc1[2], wB1, z.x); f2fma(acc1[3], wB1, z.y);
                f2fma(acc1[2], wB2, p.x); f2fma(acc1[3], wB2, p.y);
            }
        }

        // ---- LIF (hard reset) + gating sigmoid(gate)*tanh(filt) on 0/1 spikes ----
        float gbuf[8];
#pragma unroll
        for (int q = 0; q < 4; q++){
            float a0[2] = { lo32(acc0[q]), hi32(acc0[q]) };
            float a1[2] = { lo32(acc1[q]), hi32(acc1[q]) };
#pragma unroll
            for (int h = 0; h < 2; h++){
                int k = 2*q + h;
                v0[k] = v0[k] + __fdiv_rn(a0[h] - v0[k], 1.2f);
                float s0 = (v0[k] >= 0.5f) ? 1.f : 0.f;
                v0[k] *= (1.f - s0);
                v1[k] = v1[k] + __fdiv_rn(a1[h] - v1[k], 1.2f);
                float s1 = (v1[k] >= 0.5f) ? 1.f : 0.f;
                v1[k] *= (1.f - s1);
                float sg = (s0 > 0.f) ? SG1 : 0.5f;
                float th = (s1 > 0.f) ? TH1 : 0.f;
                gbuf[k] = sg * th;
            }
        }
        {
            float* grow = gsm + pair*GS_STRIDE;
            *(float4*)(grow + jA) = make_float4(gbuf[0], gbuf[1], gbuf[2], gbuf[3]);
            *(float4*)(grow + jB) = make_float4(gbuf[4], gbuf[5], gbuf[6], gbuf[7]);
        }
        __syncthreads();

        // ---- skip / res 1x1 convs over gated activations (in smem) ----
        unsigned long long skp[4], rsp[4];
#pragma unroll
        for (int q = 0; q < 4; q++){ skp[q] = 0ull; rsp[q] = 0ull; }
#pragma unroll 4
        for (int ci = 0; ci < Cn; ci++){
            float2 wv = *(const float2*)(wskr + (((ci << 6) + pair) << 1));
            unsigned long long ws = pk2(wv.x);
            unsigned long long wr = pk2(wv.y);
            const float* grow = gsm + ci*GS_STRIDE;
            ulonglong2 gA = *(const ulonglong2*)(grow + jA);
            ulonglong2 gB = *(const ulonglong2*)(grow + jB);
            f2fma(skp[0], ws, gA.x); f2fma(skp[1], ws, gA.y);
            f2fma(skp[2], ws, gB.x); f2fma(skp[3], ws, gB.y);
            f2fma(rsp[0], wr, gA.x); f2fma(rsp[1], wr, gA.y);
            f2fma(rsp[2], wr, gB.x); f2fma(rsp[3], wr, gB.y);
        }

        // ---- global update: skip += conv_skip + b ; x_new = x + conv_res + b ----
        {
            size_t gbase = ((size_t)(t*Bn + b)*Cn + pair)*Ln + l0;
            float sbp = sbv[pair], rbp = rbv[pair];
            float4 sv0 = make_float4(lo32(skp[0])+sbp, hi32(skp[0])+sbp,
                                     lo32(skp[1])+sbp, hi32(skp[1])+sbp);
            float4 sv1 = make_float4(lo32(skp[2])+sbp, hi32(skp[2])+sbp,
                                     lo32(skp[3])+sbp, hi32(skp[3])+sbp);
            float4* skA = (float4*)(g_skip + gbase + jA);
            float4* skB = (float4*)(g_skip + gbase + jB);
            if (layer != 0){
                float4 o0 = *skA, o1 = *skB;
                sv0.x += o0.x; sv0.y += o0.y; sv0.z += o0.z; sv0.w += o0.w;
                sv1.x += o1.x; sv1.y += o1.y; sv1.z += o1.z; sv1.w += o1.w;
            }
            *skA = sv0; *skB = sv1;

            float4 a0 = *(const float4*)(x_in + gbase + jA);
            float4 a1 = *(const float4*)(x_in + gbase + jB);
            a0.x += lo32(rsp[0])+rbp; a0.y += hi32(rsp[0])+rbp;
            a0.z += lo32(rsp[1])+rbp; a0.w += hi32(rsp[1])+rbp;
            a1.x += lo32(rsp[2])+rbp; a1.y += hi32(rsp[2])+rbp;
            a1.z += lo32(rsp[3])+rbp; a1.w += hi32(rsp[3])+rbp;
            *(float4*)(x_out + gbase + jA) = a0;
            *(float4*)(x_out + gbase + jB) = a1;
        }
        // no barrier needed here: next staging writes only `tile`, whose readers
        // all passed the gsm barrier above; next gsm write is behind next
        // post-staging barrier.
    }
}

// ---------------- final: relu(skip) -> 1x1 conv -> LIF -> sum over T ----------------
__global__ void __launch_bounds__(256) out_kernel(const float* __restrict__ wout,
                                                  const float* __restrict__ bout,
                                                  float* __restrict__ out){
    int g = blockIdx.x * 256 + threadIdx.x;     // (b,l)
    int b = g >> 12, l = g & (Ln - 1);
    float bo = bout[0];
    float v = 0.f, ssum = 0.f;
#pragma unroll
    for (int t = 0; t < Tn; t++){
        float acc = bo;
        const float* sk = g_skip + ((size_t)(t*Bn + b))*Cn*Ln + l;
        for (int c = 0; c < Cn; c++){
            float s = sk[(size_t)c*Ln];
            s = (s > 0.f) ? s : 0.f;
            acc += wout[c] * s;
        }
        v = v + __fdiv_rn(acc - v, 1.2f);
        float sp = (v >= 0.5f) ? 1.f : 0.f;
        v *= (1.f - sp);
        ssum += sp;
    }
    out[g] = ssum;
}

// ---------------- launch ----------------
extern "C" void kernel_launch(void* const* d_in, const int* in_sizes, int n_in,
                              void* d_out, int out_size){
    const float* audio   = (const float*)d_in[0];
    const int*   dstep   = (const int*)  d_in[1];
    const float* W_in    = (const float*)d_in[2];
    const float* b_in    = (const float*)d_in[3];
    const float* demb_w1 = (const float*)d_in[4];
    const float* demb_b1 = (const float*)d_in[5];
    const float* demb_w2 = (const float*)d_in[6];
    const float* demb_b2 = (const float*)d_in[7];
    const float* dproj_w = (const float*)d_in[8];
    const float* dproj_b = (const float*)d_in[9];
    const float* conv_w  = (const float*)d_in[10];
    const float* conv_b  = (const float*)d_in[11];
    const float* skip_w  = (const float*)d_in[12];
    const float* skip_b  = (const float*)d_in[13];
    const float* res_w   = (const float*)d_in[14];
    const float* res_b   = (const float*)d_in[15];
    const float* W_out   = (const float*)d_in[16];
    const float* b_out   = (const float*)d_in[17];

    const int SMEM_BYTES = 57920 * 4;   // 231680
    cudaFuncSetAttribute((const void*)layer_kernel,
                         cudaFuncAttributeMaxDynamicSharedMemorySize, SMEM_BYTES);

    enc_kernel<<<(Bn*Ln)/256, 256>>>(audio, W_in, b_in);

    proj_all_kernel<<<NLAYERS, 256>>>(dstep, demb_w1, demb_b1, demb_w2, demb_b2,
                                      dproj_w, dproj_b);

    int flip = 0;
    for (int i = 0; i < NLAYERS; i++){
        layer_kernel<<<dim3(Ln/TL, Bn), NTHREADS, SMEM_BYTES>>>(flip, i,
                                conv_w + i*2*Cn*Cn*3, conv_b + i*2*Cn,
                                skip_w + i*Cn*Cn,     skip_b + i*Cn,
                                res_w  + i*Cn*Cn,     res_b  + i*Cn,
                                1 << i);
        flip ^= 1;
    }

    out_kernel<<<(Bn*Ln)/256, 256>>>(W_out, b_out, (float*)d_out);
}

// round 4
// speedup vs baseline: 2.5600x; 1.1607x over previous
#include <cuda_runtime.h>
#include <math.h>

#define Tn 4
#define Bn 4
#define Cn 64
#define Ln 4096
#define NLAYERS 10
#define TL 64          // l-tile per block
#define GS_STRIDE 68   // padded row stride for gated smem
#define LTHREADS 256

// ---------------- scratch (no allocations allowed) ----------------
__device__ float g_xA[Tn*Bn*Cn*Ln];     // 16 MB
__device__ float g_xB[Tn*Bn*Cn*Ln];     // 16 MB
__device__ float g_skip[Tn*Bn*Cn*Ln];   // 16 MB
__device__ float g_proj[NLAYERS*Bn*Cn];

// ---------------- packed f32x2 helpers ----------------
__device__ __forceinline__ unsigned long long pk2(float w){
    unsigned long long r;
    asm("mov.b64 %0, {%1, %1};" : "=l"(r) : "f"(w));
    return r;
}
__device__ __forceinline__ void f2fma(unsigned long long &d, unsigned long long a, unsigned long long b){
    asm("fma.rn.f32x2 %0, %1, %2, %0;" : "+l"(d) : "l"(a), "l"(b));
}
__device__ __forceinline__ float lo32(unsigned long long v){ return __uint_as_float((unsigned)v); }
__device__ __forceinline__ float hi32(unsigned long long v){ return __uint_as_float((unsigned)(v>>32)); }

// ---------------- JAX threefry2x32 (key = (0,42)) ----------------
__device__ __forceinline__ unsigned rotl32(unsigned x, int r){ return (x<<r)|(x>>(32-r)); }

__device__ __forceinline__ void threefry_0_42(unsigned x0, unsigned x1, unsigned &o0, unsigned &o1){
    const unsigned ks0 = 0u, ks1 = 42u, ks2 = 0u ^ 42u ^ 0x1BD11BDAu;
    x0 += ks0; x1 += ks1;
#define TF_RND(r) { x0 += x1; x1 = rotl32(x1,(r)); x1 ^= x0; }
    TF_RND(13) TF_RND(15) TF_RND(26) TF_RND(6)
    x0 += ks1; x1 += ks2 + 1u;
    TF_RND(17) TF_RND(29) TF_RND(16) TF_RND(24)
    x0 += ks2; x1 += ks0 + 2u;
    TF_RND(13) TF_RND(15) TF_RND(26) TF_RND(6)
    x0 += ks0; x1 += ks1 + 3u;
    TF_RND(17) TF_RND(29) TF_RND(16) TF_RND(24)
    x0 += ks1; x1 += ks2 + 4u;
    TF_RND(13) TF_RND(15) TF_RND(26) TF_RND(6)
    x0 += ks2; x1 += ks0 + 5u;
#undef TF_RND
    o0 = x0; o1 = x1;
}
__device__ __forceinline__ float bits2unit(unsigned b){
    return __uint_as_float((b >> 9) | 0x3f800000u) - 1.0f;
}

// ---------------- encoder: poisson + input conv(1x1) + LIF ----------------
__global__ void __launch_bounds__(256) enc_kernel(const float* __restrict__ audio,
                                                  const float* __restrict__ w_in,
                                                  const float* __restrict__ b_in){
    int g = blockIdx.x * 256 + threadIdx.x;      // 0..16383  (b,l)
    int b = g >> 12, l = g & (Ln - 1);
    float a = audio[g];

    unsigned n0 = (unsigned)(b * Ln + l);        // t=0; partner t=2
    unsigned o0, o1, o2, o3;
    threefry_0_42(n0,           n0 + 32768u, o0, o2);
    threefry_0_42(n0 + 16384u,  n0 + 49152u, o1, o3);   // t=1 ; partner t=3

    float sp[4];
    sp[0] = (bits2unit(o0) < a) ? 1.f : 0.f;
    sp[1] = (bits2unit(o1) < a) ? 1.f : 0.f;
    sp[2] = (bits2unit(o2) < a) ? 1.f : 0.f;
    sp[3] = (bits2unit(o3) < a) ? 1.f : 0.f;

    for (int c = 0; c < Cn; c++){
        float w = w_in[c], bi = b_in[c];
        float v = 0.f;
#pragma unroll
        for (int t = 0; t < Tn; t++){
            float x = w * sp[t] + bi;
            v = v + __fdiv_rn(x - v, 1.2f);
            float s = (v >= 0.5f) ? 1.f : 0.f;
            v *= (1.f - s);
            int idx = ((t*Bn + b)*Cn + c)*Ln + l;
            g_xA[idx] = s;
        }
    }
}

// ---------------- ALL layers' diffusion-step embedding + projection ----------------
__global__ void __launch_bounds__(256) proj_all_kernel(const int* __restrict__ dstep,
                                                       const float* __restrict__ w1a,
                                                       const float* __restrict__ b1a,
                                                       const float* __restrict__ w2a,
                                                       const float* __restrict__ b2a,
                                                       const float* __restrict__ dpwa,
                                                       const float* __restrict__ dpba){
    int i = blockIdx.x;   // layer
    const float* w1 = w1a + i*Cn;
    const float* b1 = b1a + i*Cn;
    const float* w2 = w2a + i*Cn*Cn;
    const float* b2 = b2a + i*Cn;
    const float* dpw = dpwa + i*Cn*Cn;
    const float* dpb = dpba + i*Cn;

    __shared__ float h[Bn][Cn];
    __shared__ float e[Bn][Cn];
    int tid = threadIdx.x;
    int b = tid >> 6, c = tid & 63;

    float d = (float)dstep[b];
    float z = d * w1[c] + b1[c];
    float sg = 1.f / (1.f + expf(-z));
    h[b][c] = z * sg;                     // silu
    __syncthreads();

    float acc = b2[c];
    for (int j = 0; j < Cn; j++) acc += h[b][j] * w2[c*Cn + j];
    e[b][c] = acc;
    __syncthreads();

    float p = dpb[c];
    for (int j = 0; j < Cn; j++) p += e[b][j] * dpw[c*Cn + j];
    g_proj[i*Bn*Cn + b*Cn + c] = p;
}

// ---------------- fused layer: dilated conv + LIF + gate + skip/res 1x1 ----------------
// 256 threads: cg = tid>>3 in 0..31 -> couts {cg, cg+32, cg+64, cg+96}; lg = tid&7
// thread owns l chunks {lg*4..+3} and {32+lg*4..+3}
__global__ void __launch_bounds__(LTHREADS, 1) layer_kernel(int flip, int layer,
                                                       const float* __restrict__ wconv,
                                                       const float* __restrict__ bconv,
                                                       const float* __restrict__ wskip,
                                                       const float* __restrict__ bskip,
                                                       const float* __restrict__ wres,
                                                       const float* __restrict__ bres,
                                                       int dil){
    const float* x_in  = flip ? g_xB : g_xA;
    float*       x_out = flip ? g_xA : g_xB;

    extern __shared__ float sm[];
    float* wc4  = sm;            // [ci][32 cg][k0:4co, k1:4co, k2:4co]  24576
    float* wskr = wc4  + 24576;  // [ci][32 cg][ws,ws32,wr,wr32]          8192
    float* cb   = wskr + 8192;   // 128
    float* pr   = cb   + 128;    // 64
    float* sbv  = pr   + 64;     // 64
    float* rbv  = sbv  + 64;     // 64
    float* tile = rbv  + 64;     // 3 shifts x [64 ci][64 l]             12288
    float* gsm  = tile + 12288;  // [64][GS_STRIDE]                       4352
                                 // total = 49728 floats = 198912 B

    const int tid  = threadIdx.x;
    const int b    = blockIdx.y;
    const int l0   = blockIdx.x * TL;
    const int lg   = tid & 7;
    const int cg   = tid >> 3;     // 0..31
    const int jA   = lg * 4;
    const int jB   = 32 + lg * 4;

    // ---- coalesced weight load + scatter repack ----
    for (int i = tid; i < 24576; i += LTHREADS){
        // wconv linear: co = i/192, r = i%192, ci = r/3, k = r%3
        int co = i / 192, r = i % 192, ci = r / 3, k = r % 3;
        int g = co >> 5, cgi = co & 31;
        wc4[((ci*32 + cgi)*3 + k)*4 + g] = wconv[i];
    }
    for (int i = tid; i < 4096; i += LTHREADS){
        int co = i >> 6, ci = i & 63;
        int g = co >> 5, cgi = co & 31;
        wskr[(ci*32 + cgi)*4 + g    ] = wskip[i];
        wskr[(ci*32 + cgi)*4 + g + 2] = wres[i];
    }
    if (tid < 128) cb[tid] = bconv[tid];
    if (tid < 64){
        pr[tid]  = g_proj[layer*Bn*Cn + b*Cn + tid];
        sbv[tid] = bskip[tid];
        rbv[tid] = bres[tid];
    }
    __syncthreads();

    const float SG1 = 1.f / (1.f + expf(-1.f));
    const float TH1 = tanhf(1.f);

    // LIF membrane: 4 couts x 8 l
    float vg0[8], vg1[8], vf0[8], vf1[8];
#pragma unroll
    for (int k = 0; k < 8; k++){ vg0[k]=0.f; vg1[k]=0.f; vf0[k]=0.f; vf1[k]=0.f; }

    for (int t = 0; t < Tn; t++){
        // ---- stage (x + proj) with zero padding, 3 shifted tiles ----
        const float* xin_t = x_in + ((size_t)(t*Bn + b)) * Cn * Ln;
#pragma unroll 4
        for (int i = tid; i < 3*Cn*TL; i += LTHREADS){
            int s = i >> 12; int r = i & 4095;
            int ci = r >> 6; int j = r & 63;
            int gl = l0 + j + (s - 1) * dil;
            float val = 0.f;
            if ((unsigned)gl < (unsigned)Ln) val = xin_t[ci*Ln + gl] + pr[ci];
            tile[(s << 12) + (ci << 6) + j] = val;
        }
        __syncthreads();

        // ---- dilated conv, 4 couts x 8 l per thread ----
        unsigned long long aG0[4], aG1[4], aF0[4], aF1[4];
        {
            unsigned long long c0 = pk2(cb[cg]);
            unsigned long long c1 = pk2(cb[cg+32]);
            unsigned long long c2 = pk2(cb[cg+64]);
            unsigned long long c3 = pk2(cb[cg+96]);
#pragma unroll
            for (int q = 0; q < 4; q++){ aG0[q]=c0; aG1[q]=c1; aF0[q]=c2; aF1[q]=c3; }
        }
#pragma unroll 2
        for (int ci = 0; ci < Cn; ci++){
            const float* wrow = wc4 + (ci*32 + cg)*12;
            float4 k0 = *(const float4*)(wrow);
            float4 k1 = *(const float4*)(wrow + 4);
            float4 k2 = *(const float4*)(wrow + 8);
            const float* trow = tile + (ci << 6);
            ulonglong2 aA = *(const ulonglong2*)(trow + jA);
            ulonglong2 zA = *(const ulonglong2*)(trow + 4096 + jA);
            ulonglong2 pA = *(const ulonglong2*)(trow + 8192 + jA);
            ulonglong2 aB = *(const ulonglong2*)(trow + jB);
            ulonglong2 zB = *(const ulonglong2*)(trow + 4096 + jB);
            ulonglong2 pB = *(const ulonglong2*)(trow + 8192 + jB);
            {
                unsigned long long w0=pk2(k0.x), w1=pk2(k1.x), w2=pk2(k2.x);
                f2fma(aG0[0], w0, aA.x); f2fma(aG0[1], w0, aA.y);
                f2fma(aG0[0], w1, zA.x); f2fma(aG0[1], w1, zA.y);
                f2fma(aG0[0], w2, pA.x); f2fma(aG0[1], w2, pA.y);
                f2fma(aG0[2], w0, aB.x); f2fma(aG0[3], w0, aB.y);
                f2fma(aG0[2], w1, zB.x); f2fma(aG0[3], w1, zB.y);
                f2fma(aG0[2], w2, pB.x); f2fma(aG0[3], w2, pB.y);
            }
            {
                unsigned long long w0=pk2(k0.y), w1=pk2(k1.y), w2=pk2(k2.y);
                f2fma(aG1[0], w0, aA.x); f2fma(aG1[1], w0, aA.y);
                f2fma(aG1[0], w1, zA.x); f2fma(aG1[1], w1, zA.y);
                f2fma(aG1[0], w2, pA.x); f2fma(aG1[1], w2, pA.y);
                f2fma(aG1[2], w0, aB.x); f2fma(aG1[3], w0, aB.y);
                f2fma(aG1[2], w1, zB.x); f2fma(aG1[3], w1, zB.y);
                f2fma(aG1[2], w2, pB.x); f2fma(aG1[3], w2, pB.y);
            }
            {
                unsigned long long w0=pk2(k0.z), w1=pk2(k1.z), w2=pk2(k2.z);
                f2fma(aF0[0], w0, aA.x); f2fma(aF0[1], w0, aA.y);
                f2fma(aF0[0], w1, zA.x); f2fma(aF0[1], w1, zA.y);
                f2fma(aF0[0], w2, pA.x); f2fma(aF0[1], w2, pA.y);
                f2fma(aF0[2], w0, aB.x); f2fma(aF0[3], w0, aB.y);
                f2fma(aF0[2], w1, zB.x); f2fma(aF0[3], w1, zB.y);
                f2fma(aF0[2], w2, pB.x); f2fma(aF0[3], w2, pB.y);
            }
            {
                unsigned long long w0=pk2(k0.w), w1=pk2(k1.w), w2=pk2(k2.w);
                f2fma(aF1[0], w0, aA.x); f2fma(aF1[1], w0, aA.y);
                f2fma(aF1[0], w1, zA.x); f2fma(aF1[1], w1, zA.y);
                f2fma(aF1[0], w2, pA.x); f2fma(aF1[1], w2, pA.y);
                f2fma(aF1[2], w0, aB.x); f2fma(aF1[3], w0, aB.y);
                f2fma(aF1[2], w1, zB.x); f2fma(aF1[3], w1, zB.y);
                f2fma(aF1[2], w2, pB.x); f2fma(aF1[3], w2, pB.y);
            }
        }

        // ---- LIF (hard reset) + gating: gated ch cg from (cg, cg+64), ch cg+32 from (cg+32, cg+96)
        float gb0[8], gb1[8];
#pragma unroll
        for (int q = 0; q < 4; q++){
#pragma unroll
            for (int h = 0; h < 2; h++){
                int k = 2*q + h;
                float xg0 = h ? hi32(aG0[q]) : lo32(aG0[q]);
                float xg1 = h ? hi32(aG1[q]) : lo32(aG1[q]);
                float xf0 = h ? hi32(aF0[q]) : lo32(aF0[q]);
                float xf1 = h ? hi32(aF1[q]) : lo32(aF1[q]);

                vg0[k] = vg0[k] + __fdiv_rn(xg0 - vg0[k], 1.2f);
                float s_g0 = (vg0[k] >= 0.5f) ? 1.f : 0.f;
                vg0[k] *= (1.f - s_g0);
                vg1[k] = vg1[k] + __fdiv_rn(xg1 - vg1[k], 1.2f);
                float s_g1 = (vg1[k] >= 0.5f) ? 1.f : 0.f;
                vg1[k] *= (1.f - s_g1);
                vf0[k] = vf0[k] + __fdiv_rn(xf0 - vf0[k], 1.2f);
                float s_f0 = (vf0[k] >= 0.5f) ? 1.f : 0.f;
                vf0[k] *= (1.f - s_f0);
                vf1[k] = vf1[k] + __fdiv_rn(xf1 - vf1[k], 1.2f);
                float s_f1 = (vf1[k] >= 0.5f) ? 1.f : 0.f;
                vf1[k] *= (1.f - s_f1);

                gb0[k] = ((s_g0 > 0.f) ? SG1 : 0.5f) * ((s_f0 > 0.f) ? TH1 : 0.f);
                gb1[k] = ((s_g1 > 0.f) ? SG1 : 0.5f) * ((s_f1 > 0.f) ? TH1 : 0.f);
            }
        }
        {
            float* g0 = gsm + cg*GS_STRIDE;
            float* g1 = gsm + (cg+32)*GS_STRIDE;
            *(float4*)(g0 + jA) = make_float4(gb0[0], gb0[1], gb0[2], gb0[3]);
            *(float4*)(g0 + jB) = make_float4(gb0[4], gb0[5], gb0[6], gb0[7]);
            *(float4*)(g1 + jA) = make_float4(gb1[0], gb1[1], gb1[2], gb1[3]);
            *(float4*)(g1 + jB) = make_float4(gb1[4], gb1[5], gb1[6], gb1[7]);
        }
        __syncthreads();

        // ---- skip / res 1x1 convs: out ch cg and cg+32 ----
        unsigned long long sk0[4], sk1[4], rs0[4], rs1[4];
#pragma unroll
        for (int q = 0; q < 4; q++){ sk0[q]=0ull; sk1[q]=0ull; rs0[q]=0ull; rs1[q]=0ull; }
#pragma unroll 4
        for (int ci = 0; ci < Cn; ci++){
            float4 wv = *(const float4*)(wskr + (ci*32 + cg)*4);
            unsigned long long ws0 = pk2(wv.x), ws1 = pk2(wv.y);
            unsigned long long wr0 = pk2(wv.z), wr1 = pk2(wv.w);
            const float* grow = gsm + ci*GS_STRIDE;
            ulonglong2 gA = *(const ulonglong2*)(grow + jA);
            ulonglong2 gB = *(const ulonglong2*)(grow + jB);
            f2fma(sk0[0], ws0, gA.x); f2fma(sk0[1], ws0, gA.y);
            f2fma(sk0[2], ws0, gB.x); f2fma(sk0[3], ws0, gB.y);
            f2fma(sk1[0], ws1, gA.x); f2fma(sk1[1], ws1, gA.y);
            f2fma(sk1[2], ws1, gB.x); f2fma(sk1[3], ws1, gB.y);
            f2fma(rs0[0], wr0, gA.x); f2fma(rs0[1], wr0, gA.y);
            f2fma(rs0[2], wr0, gB.x); f2fma(rs0[3], wr0, gB.y);
            f2fma(rs1[0], wr1, gA.x); f2fma(rs1[1], wr1, gA.y);
            f2fma(rs1[2], wr1, gB.x); f2fma(rs1[3], wr1, gB.y);
        }

        // ---- global update for ch cg and cg+32 ----
#pragma unroll
        for (int ch = 0; ch < 2; ch++){
            int co = cg + ch*32;
            unsigned long long* skp = ch ? sk1 : sk0;
            unsigned long long* rsp = ch ? rs1 : rs0;
            size_t gbase = ((size_t)(t*Bn + b)*Cn + co)*Ln + l0;
            float sbp = sbv[co], rbp = rbv[co];
            float4 sv0 = make_float4(lo32(skp[0])+sbp, hi32(skp[0])+sbp,
                                     lo32(skp[1])+sbp, hi32(skp[1])+sbp);
            float4 sv1 = make_float4(lo32(skp[2])+sbp, hi32(skp[2])+sbp,
                                     lo32(skp[3])+sbp, hi32(skp[3])+sbp);
            float4* skA = (float4*)(g_skip + gbase + jA);
            float4* skB = (float4*)(g_skip + gbase + jB);
            if (layer != 0){
                float4 o0 = *skA, o1 = *skB;
                sv0.x += o0.x; sv0.y += o0.y; sv0.z += o0.z; sv0.w += o0.w;
                sv1.x += o1.x; sv1.y += o1.y; sv1.z += o1.z; sv1.w += o1.w;
            }
            *skA = sv0; *skB = sv1;

            float4 a0 = *(const float4*)(x_in + gbase + jA);
            float4 a1 = *(const float4*)(x_in + gbase + jB);
            a0.x += lo32(rsp[0])+rbp; a0.y += hi32(rsp[0])+rbp;
            a0.z += lo32(rsp[1])+rbp; a0.w += hi32(rsp[1])+rbp;
            a1.x += lo32(rsp[2])+rbp; a1.y += hi32(rsp[2])+rbp;
            a1.z += lo32(rsp[3])+rbp; a1.w += hi32(rsp[3])+rbp;
            *(float4*)(x_out + gbase + jA) = a0;
            *(float4*)(x_out + gbase + jB) = a1;
        }
        // no barrier needed: next staging writes only `tile`, whose readers all
        // passed the post-gsm barrier; next gsm write is behind next staging barrier.
    }
}

// ---------------- final: relu(skip) -> 1x1 conv -> LIF -> sum over T ----------------
__global__ void __launch_bounds__(256) out_kernel(const float* __restrict__ wout,
                                                  const float* __restrict__ bout,
                                                  float* __restrict__ out){
    int g = blockIdx.x * 256 + threadIdx.x;     // (b,l)
    int b = g >> 12, l = g & (Ln - 1);
    float bo = bout[0];
    float v = 0.f, ssum = 0.f;
#pragma unroll
    for (int t = 0; t < Tn; t++){
        float acc = bo;
        const float* sk = g_skip + ((size_t)(t*Bn + b))*Cn*Ln + l;
        for (int c = 0; c < Cn; c++){
            float s = sk[(size_t)c*Ln];
            s = (s > 0.f) ? s : 0.f;
            acc += wout[c] * s;
        }
        v = v + __fdiv_rn(acc - v, 1.2f);
        float sp = (v >= 0.5f) ? 1.f : 0.f;
        v *= (1.f - sp);
        ssum += sp;
    }
    out[g] = ssum;
}

// ---------------- launch ----------------
extern "C" void kernel_launch(void* const* d_in, const int* in_sizes, int n_in,
                              void* d_out, int out_size){
    const float* audio   = (const float*)d_in[0];
    const int*   dstep   = (const int*)  d_in[1];
    const float* W_in    = (const float*)d_in[2];
    const float* b_in    = (const float*)d_in[3];
    const float* demb_w1 = (const float*)d_in[4];
    const float* demb_b1 = (const float*)d_in[5];
    const float* demb_w2 = (const float*)d_in[6];
    const float* demb_b2 = (const float*)d_in[7];
    const float* dproj_w = (const float*)d_in[8];
    const float* dproj_b = (const float*)d_in[9];
    const float* conv_w  = (const float*)d_in[10];
    const float* conv_b  = (const float*)d_in[11];
    const float* skip_w  = (const float*)d_in[12];
    const float* skip_b  = (const float*)d_in[13];
    const float* res_w   = (const float*)d_in[14];
    const float* res_b   = (const float*)d_in[15];
    const float* W_out   = (const float*)d_in[16];
    const float* b_out   = (const float*)d_in[17];

    const int SMEM_BYTES = 49728 * 4;   // 198912
    cudaFuncSetAttribute((const void*)layer_kernel,
                         cudaFuncAttributeMaxDynamicSharedMemorySize, SMEM_BYTES);

    enc_kernel<<<(Bn*Ln)/256, 256>>>(audio, W_in, b_in);

    proj_all_kernel<<<NLAYERS, 256>>>(dstep, demb_w1, demb_b1, demb_w2, demb_b2,
                                      dproj_w, dproj_b);

    int flip = 0;
    for (int i = 0; i < NLAYERS; i++){
        layer_kernel<<<dim3(Ln/TL, Bn), LTHREADS, SMEM_BYTES>>>(flip, i,
                                conv_w + i*2*Cn*Cn*3, conv_b + i*2*Cn,
                                skip_w + i*Cn*Cn,     skip_b + i*Cn,
                                res_w  + i*Cn*Cn,     res_b  + i*Cn,
                                1 << i);
        flip ^= 1;
    }

    out_kernel<<<(Bn*Ln)/256, 256>>>(W_out, b_out, (float*)d_out);
}

// round 5
// speedup vs baseline: 2.5899x; 1.0117x over previous
#include <cuda_runtime.h>
#include <math.h>

#define Tn 4
#define Bn 4
#define Cn 64
#define Ln 4096
#define NLAYERS 10
#define TL 64          // l-tile per block
#define GS_STRIDE 68   // padded row stride for gated overlay
#define LTHREADS 256

// ---------------- scratch (no allocations allowed) ----------------
__device__ float g_xA[Tn*Bn*Cn*Ln];     // 16 MB
__device__ float g_xB[Tn*Bn*Cn*Ln];     // 16 MB
__device__ float g_skip[Tn*Bn*Cn*Ln];   // 16 MB
__device__ float g_proj[NLAYERS*Bn*Cn];

// ---------------- packed f32x2 helpers ----------------
__device__ __forceinline__ unsigned long long pk2(float w){
    unsigned long long r;
    asm("mov.b64 %0, {%1, %1};" : "=l"(r) : "f"(w));
    return r;
}
__device__ __forceinline__ void f2fma(unsigned long long &d, unsigned long long a, unsigned long long b){
    asm("fma.rn.f32x2 %0, %1, %2, %0;" : "+l"(d) : "l"(a), "l"(b));
}
__device__ __forceinline__ float lo32(unsigned long long v){ return __uint_as_float((unsigned)v); }
__device__ __forceinline__ float hi32(unsigned long long v){ return __uint_as_float((unsigned)(v>>32)); }

// ---------------- JAX threefry2x32 (key = (0,42)) ----------------
__device__ __forceinline__ unsigned rotl32(unsigned x, int r){ return (x<<r)|(x>>(32-r)); }

__device__ __forceinline__ void threefry_0_42(unsigned x0, unsigned x1, unsigned &o0, unsigned &o1){
    const unsigned ks0 = 0u, ks1 = 42u, ks2 = 0u ^ 42u ^ 0x1BD11BDAu;
    x0 += ks0; x1 += ks1;
#define TF_RND(r) { x0 += x1; x1 = rotl32(x1,(r)); x1 ^= x0; }
    TF_RND(13) TF_RND(15) TF_RND(26) TF_RND(6)
    x0 += ks1; x1 += ks2 + 1u;
    TF_RND(17) TF_RND(29) TF_RND(16) TF_RND(24)
    x0 += ks2; x1 += ks0 + 2u;
    TF_RND(13) TF_RND(15) TF_RND(26) TF_RND(6)
    x0 += ks0; x1 += ks1 + 3u;
    TF_RND(17) TF_RND(29) TF_RND(16) TF_RND(24)
    x0 += ks1; x1 += ks2 + 4u;
    TF_RND(13) TF_RND(15) TF_RND(26) TF_RND(6)
    x0 += ks2; x1 += ks0 + 5u;
#undef TF_RND
    o0 = x0; o1 = x1;
}
__device__ __forceinline__ float bits2unit(unsigned b){
    return __uint_as_float((b >> 9) | 0x3f800000u) - 1.0f;
}

// ---------------- encoder: poisson + input conv(1x1) + LIF ----------------
__global__ void __launch_bounds__(256) enc_kernel(const float* __restrict__ audio,
                                                  const float* __restrict__ w_in,
                                                  const float* __restrict__ b_in){
    int g = blockIdx.x * 256 + threadIdx.x;      // 0..16383  (b,l)
    int b = g >> 12, l = g & (Ln - 1);
    float a = audio[g];

    unsigned n0 = (unsigned)(b * Ln + l);        // t=0; partner t=2
    unsigned o0, o1, o2, o3;
    threefry_0_42(n0,           n0 + 32768u, o0, o2);
    threefry_0_42(n0 + 16384u,  n0 + 49152u, o1, o3);   // t=1 ; partner t=3

    float sp[4];
    sp[0] = (bits2unit(o0) < a) ? 1.f : 0.f;
    sp[1] = (bits2unit(o1) < a) ? 1.f : 0.f;
    sp[2] = (bits2unit(o2) < a) ? 1.f : 0.f;
    sp[3] = (bits2unit(o3) < a) ? 1.f : 0.f;

    for (int c = 0; c < Cn; c++){
        float w = w_in[c], bi = b_in[c];
        float v = 0.f;
#pragma unroll
        for (int t = 0; t < Tn; t++){
            float x = w * sp[t] + bi;
            v = v + __fdiv_rn(x - v, 1.2f);
            float s = (v >= 0.5f) ? 1.f : 0.f;
            v *= (1.f - s);
            int idx = ((t*Bn + b)*Cn + c)*Ln + l;
            g_xA[idx] = s;
        }
    }
}

// ---------------- ALL layers' diffusion-step embedding + projection ----------------
__global__ void __launch_bounds__(256) proj_all_kernel(const int* __restrict__ dstep,
                                                       const float* __restrict__ w1a,
                                                       const float* __restrict__ b1a,
                                                       const float* __restrict__ w2a,
                                                       const float* __restrict__ b2a,
                                                       const float* __restrict__ dpwa,
                                                       const float* __restrict__ dpba){
    int i = blockIdx.x;   // layer
    const float* w1 = w1a + i*Cn;
    const float* b1 = b1a + i*Cn;
    const float* w2 = w2a + i*Cn*Cn;
    const float* b2 = b2a + i*Cn;
    const float* dpw = dpwa + i*Cn*Cn;
    const float* dpb = dpba + i*Cn;

    __shared__ float h[Bn][Cn];
    __shared__ float e[Bn][Cn];
    int tid = threadIdx.x;
    int b = tid >> 6, c = tid & 63;

    float d = (float)dstep[b];
    float z = d * w1[c] + b1[c];
    float sg = 1.f / (1.f + expf(-z));
    h[b][c] = z * sg;                     // silu
    __syncthreads();

    float acc = b2[c];
    for (int j = 0; j < Cn; j++) acc += h[b][j] * w2[c*Cn + j];
    e[b][c] = acc;
    __syncthreads();

    float p = dpb[c];
    for (int j = 0; j < Cn; j++) p += e[b][j] * dpw[c*Cn + j];
    g_proj[i*Bn*Cn + b*Cn + c] = p;
}

// ---------------- fused layer: 2-timestep dilated conv + LIF + gate + skip/res 1x1 ----
// 256 threads: cg = tid>>3 (couts {cg, cg+32, cg+64, cg+96}); lg = tid&7
// thread owns l chunks {lg*4..+3} and {32+lg*4..+3}; TWO timesteps per pass.
__global__ void __launch_bounds__(LTHREADS, 1) layer_kernel(int flip, int layer,
                                                       const float* __restrict__ wconv,
                                                       const float* __restrict__ bconv,
                                                       const float* __restrict__ wskip,
                                                       const float* __restrict__ bskip,
                                                       const float* __restrict__ wres,
                                                       const float* __restrict__ bres,
                                                       int dil){
    const float* x_in  = flip ? g_xB : g_xA;
    float*       x_out = flip ? g_xA : g_xB;

    extern __shared__ float sm[];
    float* wc4  = sm;            // [ci][32 cg][k0:4co, k1:4co, k2:4co]  24576
    float* wskr = wc4  + 24576;  // [ci][32 cg][ws,ws32,wr,wr32]          8192
    float* cb   = wskr + 8192;   // 128
    float* pr   = cb   + 128;    // 64
    float* sbv  = pr   + 64;     // 64
    float* rbv  = sbv  + 64;     // 64
    float* tile = rbv  + 64;     // 2 timesteps x 3 shifts x [64 ci][64 l] = 24576
                                 // gated overlay: gsm_t = tile + t*12288 (64 x 68)
                                 // total = 57664 floats = 230656 B

    const int tid  = threadIdx.x;
    const int b    = blockIdx.y;
    const int l0   = blockIdx.x * TL;
    const int lg   = tid & 7;
    const int cg   = tid >> 3;     // 0..31
    const int jA   = lg * 4;
    const int jB   = 32 + lg * 4;

    // ---- coalesced weight load + scatter repack ----
    for (int i = tid; i < 24576; i += LTHREADS){
        int co = i / 192, r = i % 192, ci = r / 3, k = r % 3;
        int g = co >> 5, cgi = co & 31;
        wc4[((ci*32 + cgi)*3 + k)*4 + g] = wconv[i];
    }
    for (int i = tid; i < 4096; i += LTHREADS){
        int co = i >> 6, ci = i & 63;
        int g = co >> 5, cgi = co & 31;
        wskr[(ci*32 + cgi)*4 + g    ] = wskip[i];
        wskr[(ci*32 + cgi)*4 + g + 2] = wres[i];
    }
    if (tid < 128) cb[tid] = bconv[tid];
    if (tid < 64){
        pr[tid]  = g_proj[layer*Bn*Cn + b*Cn + tid];
        sbv[tid] = bskip[tid];
        rbv[tid] = bres[tid];
    }
    __syncthreads();

    const float SG1 = 1.f / (1.f + expf(-1.f));
    const float TH1 = tanhf(1.f);

    const unsigned long long cb0 = pk2(cb[cg]);
    const unsigned long long cb1 = pk2(cb[cg+32]);
    const unsigned long long cb2 = pk2(cb[cg+64]);
    const unsigned long long cb3 = pk2(cb[cg+96]);
    const float sb0 = sbv[cg], sb1 = sbv[cg+32];
    const float rb0 = rbv[cg], rb1 = rbv[cg+32];

    // LIF membrane: 4 couts x 8 l (persist across both tt iterations)
    float vg0[8], vg1[8], vf0[8], vf1[8];
#pragma unroll
    for (int k = 0; k < 8; k++){ vg0[k]=0.f; vg1[k]=0.f; vf0[k]=0.f; vf1[k]=0.f; }

    for (int tt = 0; tt < 2; tt++){
        const int t0 = tt * 2;

        // ---- stage 2 timestep tiles (x + proj) with zero padding, 3 shifts each ----
        // linear i = k*12288 + s*4096 + ci*64 + j
#pragma unroll 4
        for (int i = tid; i < 2*3*Cn*TL; i += LTHREADS){
            int k  = i / 12288;
            int r2 = i - k*12288;
            int s  = r2 >> 12;
            int r  = r2 & 4095;
            int ci = r >> 6; int j = r & 63;
            int gl = l0 + j + (s - 1) * dil;
            float val = 0.f;
            if ((unsigned)gl < (unsigned)Ln)
                val = x_in[((size_t)((t0+k)*Bn + b)*Cn + ci)*Ln + gl] + pr[ci];
            tile[i] = val;
        }
        __syncthreads();   // S1: tiles ready

        // ---- dilated conv, 4 couts x 8 l x 2 timesteps per thread ----
        unsigned long long aG0[2][4], aG1[2][4], aF0[2][4], aF1[2][4];
#pragma unroll
        for (int k = 0; k < 2; k++)
#pragma unroll
        for (int q = 0; q < 4; q++){ aG0[k][q]=cb0; aG1[k][q]=cb1; aF0[k][q]=cb2; aF1[k][q]=cb3; }

#pragma unroll 2
        for (int ci = 0; ci < Cn; ci++){
            const float* wrow = wc4 + (ci*32 + cg)*12;
            float4 k0 = *(const float4*)(wrow);
            float4 k1 = *(const float4*)(wrow + 4);
            float4 k2 = *(const float4*)(wrow + 8);
            unsigned long long w00=pk2(k0.x), w01=pk2(k1.x), w02=pk2(k2.x);
            unsigned long long w10=pk2(k0.y), w11=pk2(k1.y), w12=pk2(k2.y);
            unsigned long long w20=pk2(k0.z), w21=pk2(k1.z), w22=pk2(k2.z);
            unsigned long long w30=pk2(k0.w), w31=pk2(k1.w), w32=pk2(k2.w);
#pragma unroll
            for (int k = 0; k < 2; k++){
                const float* trow = tile + k*12288 + (ci << 6);
                ulonglong2 aA = *(const ulonglong2*)(trow + jA);
                ulonglong2 zA = *(const ulonglong2*)(trow + 4096 + jA);
                ulonglong2 pA = *(const ulonglong2*)(trow + 8192 + jA);
                ulonglong2 aB = *(const ulonglong2*)(trow + jB);
                ulonglong2 zB = *(const ulonglong2*)(trow + 4096 + jB);
                ulonglong2 pB = *(const ulonglong2*)(trow + 8192 + jB);
                f2fma(aG0[k][0], w00, aA.x); f2fma(aG0[k][1], w00, aA.y);
                f2fma(aG0[k][0], w01, zA.x); f2fma(aG0[k][1], w01, zA.y);
                f2fma(aG0[k][0], w02, pA.x); f2fma(aG0[k][1], w02, pA.y);
                f2fma(aG0[k][2], w00, aB.x); f2fma(aG0[k][3], w00, aB.y);
                f2fma(aG0[k][2], w01, zB.x); f2fma(aG0[k][3], w01, zB.y);
                f2fma(aG0[k][2], w02, pB.x); f2fma(aG0[k][3], w02, pB.y);

                f2fma(aG1[k][0], w10, aA.x); f2fma(aG1[k][1], w10, aA.y);
                f2fma(aG1[k][0], w11, zA.x); f2fma(aG1[k][1], w11, zA.y);
                f2fma(aG1[k][0], w12, pA.x); f2fma(aG1[k][1], w12, pA.y);
                f2fma(aG1[k][2], w10, aB.x); f2fma(aG1[k][3], w10, aB.y);
                f2fma(aG1[k][2], w11, zB.x); f2fma(aG1[k][3], w11, zB.y);
                f2fma(aG1[k][2], w12, pB.x); f2fma(aG1[k][3], w12, pB.y);

                f2fma(aF0[k][0], w20, aA.x); f2fma(aF0[k][1], w20, aA.y);
                f2fma(aF0[k][0], w21, zA.x); f2fma(aF0[k][1], w21, zA.y);
                f2fma(aF0[k][0], w22, pA.x); f2fma(aF0[k][1], w22, pA.y);
                f2fma(aF0[k][2], w20, aB.x); f2fma(aF0[k][3], w20, aB.y);
                f2fma(aF0[k][2], w21, zB.x); f2fma(aF0[k][3], w21, zB.y);
                f2fma(aF0[k][2], w22, pB.x); f2fma(aF0[k][3], w22, pB.y);

                f2fma(aF1[k][0], w30, aA.x); f2fma(aF1[k][1], w30, aA.y);
                f2fma(aF1[k][0], w31, zA.x); f2fma(aF1[k][1], w31, zA.y);
                f2fma(aF1[k][0], w32, pA.x); f2fma(aF1[k][1], w32, pA.y);
                f2fma(aF1[k][2], w30, aB.x); f2fma(aF1[k][3], w30, aB.y);
                f2fma(aF1[k][2], w31, zB.x); f2fma(aF1[k][3], w31, zB.y);
                f2fma(aF1[k][2], w32, pB.x); f2fma(aF1[k][3], w32, pB.y);
            }
        }

        // ---- LIF (hard reset) + gating, both timesteps in order ----
        float gb0[2][8], gb1[2][8];
#pragma unroll
        for (int k = 0; k < 2; k++){
#pragma unroll
            for (int q = 0; q < 4; q++){
#pragma unroll
                for (int h = 0; h < 2; h++){
                    int idx = 2*q + h;
                    float xg0 = h ? hi32(aG0[k][q]) : lo32(aG0[k][q]);
                    float xg1 = h ? hi32(aG1[k][q]) : lo32(aG1[k][q]);
                    float xf0 = h ? hi32(aF0[k][q]) : lo32(aF0[k][q]);
                    float xf1 = h ? hi32(aF1[k][q]) : lo32(aF1[k][q]);

                    vg0[idx] = vg0[idx] + __fdiv_rn(xg0 - vg0[idx], 1.2f);
                    float s_g0 = (vg0[idx] >= 0.5f) ? 1.f : 0.f;
                    vg0[idx] *= (1.f - s_g0);
                    vg1[idx] = vg1[idx] + __fdiv_rn(xg1 - vg1[idx], 1.2f);
                    float s_g1 = (vg1[idx] >= 0.5f) ? 1.f : 0.f;
                    vg1[idx] *= (1.f - s_g1);
                    vf0[idx] = vf0[idx] + __fdiv_rn(xf0 - vf0[idx], 1.2f);
                    float s_f0 = (vf0[idx] >= 0.5f) ? 1.f : 0.f;
                    vf0[idx] *= (1.f - s_f0);
                    vf1[idx] = vf1[idx] + __fdiv_rn(xf1 - vf1[idx], 1.2f);
                    float s_f1 = (vf1[idx] >= 0.5f) ? 1.f : 0.f;
                    vf1[idx] *= (1.f - s_f1);

                    gb0[k][idx] = ((s_g0 > 0.f) ? SG1 : 0.5f) * ((s_f0 > 0.f) ? TH1 : 0.f);
                    gb1[k][idx] = ((s_g1 > 0.f) ? SG1 : 0.5f) * ((s_f1 > 0.f) ? TH1 : 0.f);
                }
            }
        }
        __syncthreads();   // S2: all conv reads of tile done -> safe to overlay gated

#pragma unroll
        for (int k = 0; k < 2; k++){
            float* g0 = tile + k*12288 + cg*GS_STRIDE;
            float* g1 = tile + k*12288 + (cg+32)*GS_STRIDE;
            *(float4*)(g0 + jA) = make_float4(gb0[k][0], gb0[k][1], gb0[k][2], gb0[k][3]);
            *(float4*)(g0 + jB) = make_float4(gb0[k][4], gb0[k][5], gb0[k][6], gb0[k][7]);
            *(float4*)(g1 + jA) = make_float4(gb1[k][0], gb1[k][1], gb1[k][2], gb1[k][3]);
            *(float4*)(g1 + jB) = make_float4(gb1[k][4], gb1[k][5], gb1[k][6], gb1[k][7]);
        }
        __syncthreads();   // S3: gated visible

        // ---- skip / res 1x1 convs for both timesteps ----
        unsigned long long sk0[2][4], sk1[2][4], rs0[2][4], rs1[2][4];
#pragma unroll
        for (int k = 0; k < 2; k++)
#pragma unroll
        for (int q = 0; q < 4; q++){ sk0[k][q]=0ull; sk1[k][q]=0ull; rs0[k][q]=0ull; rs1[k][q]=0ull; }

#pragma unroll 4
        for (int ci = 0; ci < Cn; ci++){
            float4 wv = *(const float4*)(wskr + (ci*32 + cg)*4);
            unsigned long long ws0 = pk2(wv.x), ws1 = pk2(wv.y);
            unsigned long long wr0 = pk2(wv.z), wr1 = pk2(wv.w);
#pragma unroll
            for (int k = 0; k < 2; k++){
                const float* grow = tile + k*12288 + ci*GS_STRIDE;
                ulonglong2 gA = *(const ulonglong2*)(grow + jA);
                ulonglong2 gB = *(const ulonglong2*)(grow + jB);
                f2fma(sk0[k][0], ws0, gA.x); f2fma(sk0[k][1], ws0, gA.y);
                f2fma(sk0[k][2], ws0, gB.x); f2fma(sk0[k][3], ws0, gB.y);
                f2fma(sk1[k][0], ws1, gA.x); f2fma(sk1[k][1], ws1, gA.y);
                f2fma(sk1[k][2], ws1, gB.x); f2fma(sk1[k][3], ws1, gB.y);
                f2fma(rs0[k][0], wr0, gA.x); f2fma(rs0[k][1], wr0, gA.y);
                f2fma(rs0[k][2], wr0, gB.x); f2fma(rs0[k][3], wr0, gB.y);
                f2fma(rs1[k][0], wr1, gA.x); f2fma(rs1[k][1], wr1, gA.y);
                f2fma(rs1[k][2], wr1, gB.x); f2fma(rs1[k][3], wr1, gB.y);
            }
        }

        // ---- global update for both timesteps, ch cg and cg+32 ----
#pragma unroll
        for (int k = 0; k < 2; k++){
#pragma unroll
            for (int ch = 0; ch < 2; ch++){
                int co = cg + ch*32;
                unsigned long long* skp = ch ? sk1[k] : sk0[k];
                unsigned long long* rsp = ch ? rs1[k] : rs0[k];
                float sbp = ch ? sb1 : sb0;
                float rbp = ch ? rb1 : rb0;
                size_t gbase = ((size_t)((t0+k)*Bn + b)*Cn + co)*Ln + l0;
                float4 sv0 = make_float4(lo32(skp[0])+sbp, hi32(skp[0])+sbp,
                                         lo32(skp[1])+sbp, hi32(skp[1])+sbp);
                float4 sv1 = make_float4(lo32(skp[2])+sbp, hi32(skp[2])+sbp,
                                         lo32(skp[3])+sbp, hi32(skp[3])+sbp);
                float4* skA = (float4*)(g_skip + gbase + jA);
                float4* skB = (float4*)(g_skip + gbase + jB);
                if (layer != 0){
                    float4 o0 = *skA, o1 = *skB;
                    sv0.x += o0.x; sv0.y += o0.y; sv0.z += o0.z; sv0.w += o0.w;
                    sv1.x += o1.x; sv1.y += o1.y; sv1.z += o1.z; sv1.w += o1.w;
                }
                *skA = sv0; *skB = sv1;

                float4 a0 = *(const float4*)(x_in + gbase + jA);
                float4 a1 = *(const float4*)(x_in + gbase + jB);
                a0.x += lo32(rsp[0])+rbp; a0.y += hi32(rsp[0])+rbp;
                a0.z += lo32(rsp[1])+rbp; a0.w += hi32(rsp[1])+rbp;
                a1.x += lo32(rsp[2])+rbp; a1.y += hi32(rsp[2])+rbp;
                a1.z += lo32(rsp[3])+rbp; a1.w += hi32(rsp[3])+rbp;
                *(float4*)(x_out + gbase + jA) = a0;
                *(float4*)(x_out + gbase + jB) = a1;
            }
        }
        __syncthreads();   // S4: 1x1 reads of gated overlay done -> next staging may write tile
    }
}

// ---------------- final: relu(skip) -> 1x1 conv -> LIF -> sum over T ----------------
__global__ void __launch_bounds__(256) out_kernel(const float* __restrict__ wout,
                                                  const float* __restrict__ bout,
                                                  float* __restrict__ out){
    int g = blockIdx.x * 256 + threadIdx.x;     // (b,l)
    int b = g >> 12, l = g & (Ln - 1);
    float bo = bout[0];
    float v = 0.f, ssum = 0.f;
#pragma unroll
    for (int t = 0; t < Tn; t++){
        float acc = bo;
        const float* sk = g_skip + ((size_t)(t*Bn + b))*Cn*Ln + l;
        for (int c = 0; c < Cn; c++){
            float s = sk[(size_t)c*Ln];
            s = (s > 0.f) ? s : 0.f;
            acc += wout[c] * s;
        }
        v = v + __fdiv_rn(acc - v, 1.2f);
        float sp = (v >= 0.5f) ? 1.f : 0.f;
        v *= (1.f - sp);
        ssum += sp;
    }
    out[g] = ssum;
}

// ---------------- launch ----------------
extern "C" void kernel_launch(void* const* d_in, const int* in_sizes, int n_in,
                              void* d_out, int out_size){
    const float* audio   = (const float*)d_in[0];
    const int*   dstep   = (const int*)  d_in[1];
    const float* W_in    = (const float*)d_in[2];
    const float* b_in    = (const float*)d_in[3];
    const float* demb_w1 = (const float*)d_in[4];
    const float* demb_b1 = (const float*)d_in[5];
    const float* demb_w2 = (const float*)d_in[6];
    const float* demb_b2 = (const float*)d_in[7];
    const float* dproj_w = (const float*)d_in[8];
    const float* dproj_b = (const float*)d_in[9];
    const float* conv_w  = (const float*)d_in[10];
    const float* conv_b  = (const float*)d_in[11];
    const float* skip_w  = (const float*)d_in[12];
    const float* skip_b  = (const float*)d_in[13];
    const float* res_w   = (const float*)d_in[14];
    const float* res_b   = (const float*)d_in[15];
    const float* W_out   = (const float*)d_in[16];
    const float* b_out   = (const float*)d_in[17];

    const int SMEM_BYTES = 57664 * 4;   // 230656
    cudaFuncSetAttribute((const void*)layer_kernel,
                         cudaFuncAttributeMaxDynamicSharedMemorySize, SMEM_BYTES);

    enc_kernel<<<(Bn*Ln)/256, 256>>>(audio, W_in, b_in);

    proj_all_kernel<<<NLAYERS, 256>>>(dstep, demb_w1, demb_b1, demb_w2, demb_b2,
                                      dproj_w, dproj_b);

    int flip = 0;
    for (int i = 0; i < NLAYERS; i++){
        layer_kernel<<<dim3(Ln/TL, Bn), LTHREADS, SMEM_BYTES>>>(flip, i,
                                conv_w + i*2*Cn*Cn*3, conv_b + i*2*Cn,
                                skip_w + i*Cn*Cn,     skip_b + i*Cn,
                                res_w  + i*Cn*Cn,     res_b  + i*Cn,
                                1 << i);
        flip ^= 1;
    }

    out_kernel<<<(Bn*Ln)/256, 256>>>(W_out, b_out, (float*)d_out);
}

// round 6
// speedup vs baseline: 2.9525x; 1.1400x over previous
#include <cuda_runtime.h>
#include <math.h>

#define Tn 4
#define Bn 4
#define Cn 64
#define Ln 4096
#define NLAYERS 10
#define TL 64          // l-tile per block
#define GS_STRIDE 68   // padded row stride for gated overlay
#define LTHREADS 512

// ---------------- scratch (no allocations allowed) ----------------
__device__ float g_xA[Tn*Bn*Cn*Ln];     // 16 MB
__device__ float g_xB[Tn*Bn*Cn*Ln];     // 16 MB
__device__ float g_skip[Tn*Bn*Cn*Ln];   // 16 MB
__device__ float g_proj[NLAYERS*Bn*Cn];

// ---------------- packed f32x2 helpers ----------------
__device__ __forceinline__ unsigned long long pk2(float w){
    unsigned long long r;
    asm("mov.b64 %0, {%1, %1};" : "=l"(r) : "f"(w));
    return r;
}
__device__ __forceinline__ void f2fma(unsigned long long &d, unsigned long long a, unsigned long long b){
    asm("fma.rn.f32x2 %0, %1, %2, %0;" : "+l"(d) : "l"(a), "l"(b));
}
__device__ __forceinline__ float lo32(unsigned long long v){ return __uint_as_float((unsigned)v); }
__device__ __forceinline__ float hi32(unsigned long long v){ return __uint_as_float((unsigned)(v>>32)); }

// ---------------- JAX threefry2x32 (key = (0,42)) ----------------
__device__ __forceinline__ unsigned rotl32(unsigned x, int r){ return (x<<r)|(x>>(32-r)); }

__device__ __forceinline__ void threefry_0_42(unsigned x0, unsigned x1, unsigned &o0, unsigned &o1){
    const unsigned ks0 = 0u, ks1 = 42u, ks2 = 0u ^ 42u ^ 0x1BD11BDAu;
    x0 += ks0; x1 += ks1;
#define TF_RND(r) { x0 += x1; x1 = rotl32(x1,(r)); x1 ^= x0; }
    TF_RND(13) TF_RND(15) TF_RND(26) TF_RND(6)
    x0 += ks1; x1 += ks2 + 1u;
    TF_RND(17) TF_RND(29) TF_RND(16) TF_RND(24)
    x0 += ks2; x1 += ks0 + 2u;
    TF_RND(13) TF_RND(15) TF_RND(26) TF_RND(6)
    x0 += ks0; x1 += ks1 + 3u;
    TF_RND(17) TF_RND(29) TF_RND(16) TF_RND(24)
    x0 += ks1; x1 += ks2 + 4u;
    TF_RND(13) TF_RND(15) TF_RND(26) TF_RND(6)
    x0 += ks2; x1 += ks0 + 5u;
#undef TF_RND
    o0 = x0; o1 = x1;
}
__device__ __forceinline__ float bits2unit(unsigned b){
    return __uint_as_float((b >> 9) | 0x3f800000u) - 1.0f;
}

// ---------------- encoder: poisson + input conv(1x1) + LIF ----------------
__global__ void __launch_bounds__(256) enc_kernel(const float* __restrict__ audio,
                                                  const float* __restrict__ w_in,
                                                  const float* __restrict__ b_in){
    int g = blockIdx.x * 256 + threadIdx.x;      // 0..16383  (b,l)
    int b = g >> 12, l = g & (Ln - 1);
    float a = audio[g];

    unsigned n0 = (unsigned)(b * Ln + l);        // t=0; partner t=2
    unsigned o0, o1, o2, o3;
    threefry_0_42(n0,           n0 + 32768u, o0, o2);
    threefry_0_42(n0 + 16384u,  n0 + 49152u, o1, o3);   // t=1 ; partner t=3

    float sp[4];
    sp[0] = (bits2unit(o0) < a) ? 1.f : 0.f;
    sp[1] = (bits2unit(o1) < a) ? 1.f : 0.f;
    sp[2] = (bits2unit(o2) < a) ? 1.f : 0.f;
    sp[3] = (bits2unit(o3) < a) ? 1.f : 0.f;

    for (int c = 0; c < Cn; c++){
        float w = w_in[c], bi = b_in[c];
        float v = 0.f;
#pragma unroll
        for (int t = 0; t < Tn; t++){
            float x = w * sp[t] + bi;
            v = v + __fdiv_rn(x - v, 1.2f);
            float s = (v >= 0.5f) ? 1.f : 0.f;
            v *= (1.f - s);
            int idx = ((t*Bn + b)*Cn + c)*Ln + l;
            g_xA[idx] = s;
        }
    }
}

// ---------------- ALL layers' diffusion-step embedding + projection ----------------
__global__ void __launch_bounds__(256) proj_all_kernel(const int* __restrict__ dstep,
                                                       const float* __restrict__ w1a,
                                                       const float* __restrict__ b1a,
                                                       const float* __restrict__ w2a,
                                                       const float* __restrict__ b2a,
                                                       const float* __restrict__ dpwa,
                                                       const float* __restrict__ dpba){
    int i = blockIdx.x;   // layer
    const float* w1 = w1a + i*Cn;
    const float* b1 = b1a + i*Cn;
    const float* w2 = w2a + i*Cn*Cn;
    const float* b2 = b2a + i*Cn;
    const float* dpw = dpwa + i*Cn*Cn;
    const float* dpb = dpba + i*Cn;

    __shared__ float h[Bn][Cn];
    __shared__ float e[Bn][Cn];
    int tid = threadIdx.x;
    int b = tid >> 6, c = tid & 63;

    float d = (float)dstep[b];
    float z = d * w1[c] + b1[c];
    float sg = 1.f / (1.f + expf(-z));
    h[b][c] = z * sg;                     // silu
    __syncthreads();

    float acc = b2[c];
    for (int j = 0; j < Cn; j++) acc += h[b][j] * w2[c*Cn + j];
    e[b][c] = acc;
    __syncthreads();

    float p = dpb[c];
    for (int j = 0; j < Cn; j++) p += e[b][j] * dpw[c*Cn + j];
    g_proj[i*Bn*Cn + b*Cn + c] = p;
}

// ---------------- fused layer: 2-timestep dilated conv + LIF + gate + skip/res 1x1 ----
// 512 threads: cg = tid>>4 (couts {cg, cg+32, cg+64, cg+96}); lg = tid&15 -> 4 l each
__global__ void __launch_bounds__(LTHREADS, 1) layer_kernel(int flip, int layer,
                                                       const float* __restrict__ wconv,
                                                       const float* __restrict__ bconv,
                                                       const float* __restrict__ wskip,
                                                       const float* __restrict__ bskip,
                                                       const float* __restrict__ wres,
                                                       const float* __restrict__ bres,
                                                       int dil){
    const float* x_in  = flip ? g_xB : g_xA;
    float*       x_out = flip ? g_xA : g_xB;

    extern __shared__ float sm[];
    float* wc4  = sm;            // [ci][32 cg][k0:4co, k1:4co, k2:4co]  24576
    float* wskr = wc4  + 24576;  // [ci][32 cg][ws,ws32,wr,wr32]          8192
    float* cb   = wskr + 8192;   // 128
    float* pr   = cb   + 128;    // 64
    float* sbv  = pr   + 64;     // 64
    float* rbv  = sbv  + 64;     // 64
    float* tile = rbv  + 64;     // 2 timesteps x 3 shifts x [64 ci][64 l] = 24576
                                 // gated overlay: gsm_t = tile + t*12288 (64 x 68)
                                 // total = 57664 floats = 230656 B

    const int tid  = threadIdx.x;
    const int b    = blockIdx.y;
    const int l0   = blockIdx.x * TL;
    const int lg   = tid & 15;
    const int cg   = tid >> 4;     // 0..31
    const int jA   = lg * 4;

    // ---- coalesced weight load + scatter repack ----
    for (int i = tid; i < 24576; i += LTHREADS){
        int co = i / 192, r = i % 192, ci = r / 3, k = r % 3;
        int g = co >> 5, cgi = co & 31;
        wc4[((ci*32 + cgi)*3 + k)*4 + g] = wconv[i];
    }
    for (int i = tid; i < 4096; i += LTHREADS){
        int co = i >> 6, ci = i & 63;
        int g = co >> 5, cgi = co & 31;
        wskr[(ci*32 + cgi)*4 + g    ] = wskip[i];
        wskr[(ci*32 + cgi)*4 + g + 2] = wres[i];
    }
    if (tid < 128) cb[tid] = bconv[tid];
    if (tid < 64){
        pr[tid]  = g_proj[layer*Bn*Cn + b*Cn + tid];
        sbv[tid] = bskip[tid];
        rbv[tid] = bres[tid];
    }
    __syncthreads();

    const float SG1 = 1.f / (1.f + expf(-1.f));
    const float TH1 = tanhf(1.f);

    const unsigned long long cb0 = pk2(cb[cg]);
    const unsigned long long cb1 = pk2(cb[cg+32]);
    const unsigned long long cb2 = pk2(cb[cg+64]);
    const unsigned long long cb3 = pk2(cb[cg+96]);
    const float sb0 = sbv[cg], sb1 = sbv[cg+32];
    const float rb0 = rbv[cg], rb1 = rbv[cg+32];

    // LIF membrane: 4 couts x 4 l (persist across tt iterations)
    float vg0[4], vg1[4], vf0[4], vf1[4];
#pragma unroll
    for (int k = 0; k < 4; k++){ vg0[k]=0.f; vg1[k]=0.f; vf0[k]=0.f; vf1[k]=0.f; }

    for (int tt = 0; tt < 2; tt++){
        const int t0 = tt * 2;

        // ---- stage 2 timestep tiles (x + proj) with zero padding, 3 shifts each ----
#pragma unroll
        for (int k = 0; k < 2; k++){
            const float* xin_t = x_in + ((size_t)((t0+k)*Bn + b)) * Cn * Ln;
            float* tk = tile + k*12288;
#pragma unroll 4
            for (int i = tid; i < 3*Cn*TL; i += LTHREADS){
                int s  = i >> 12;
                int r  = i & 4095;
                int ci = r >> 6; int j = r & 63;
                int gl = l0 + j + (s - 1) * dil;
                float val = 0.f;
                if ((unsigned)gl < (unsigned)Ln) val = xin_t[ci*Ln + gl] + pr[ci];
                tk[i] = val;
            }
        }
        __syncthreads();   // S1: tiles ready

        // ---- dilated conv, 4 couts x 4 l x 2 timesteps per thread ----
        unsigned long long aG0[2][2], aG1[2][2], aF0[2][2], aF1[2][2];
#pragma unroll
        for (int k = 0; k < 2; k++)
#pragma unroll
        for (int q = 0; q < 2; q++){ aG0[k][q]=cb0; aG1[k][q]=cb1; aF0[k][q]=cb2; aF1[k][q]=cb3; }

#pragma unroll 2
        for (int ci = 0; ci < Cn; ci++){
            const float* wrow = wc4 + (ci*32 + cg)*12;
            float4 k0 = *(const float4*)(wrow);
            float4 k1 = *(const float4*)(wrow + 4);
            float4 k2 = *(const float4*)(wrow + 8);
            unsigned long long w00=pk2(k0.x), w01=pk2(k1.x), w02=pk2(k2.x);
            unsigned long long w10=pk2(k0.y), w11=pk2(k1.y), w12=pk2(k2.y);
            unsigned long long w20=pk2(k0.z), w21=pk2(k1.z), w22=pk2(k2.z);
            unsigned long long w30=pk2(k0.w), w31=pk2(k1.w), w32=pk2(k2.w);
#pragma unroll
            for (int k = 0; k < 2; k++){
                const float* trow = tile + k*12288 + (ci << 6);
                ulonglong2 aA = *(const ulonglong2*)(trow + jA);
                ulonglong2 zA = *(const ulonglong2*)(trow + 4096 + jA);
                ulonglong2 pA = *(const ulonglong2*)(trow + 8192 + jA);
                f2fma(aG0[k][0], w00, aA.x); f2fma(aG0[k][1], w00, aA.y);
                f2fma(aG0[k][0], w01, zA.x); f2fma(aG0[k][1], w01, zA.y);
                f2fma(aG0[k][0], w02, pA.x); f2fma(aG0[k][1], w02, pA.y);

                f2fma(aG1[k][0], w10, aA.x); f2fma(aG1[k][1], w10, aA.y);
                f2fma(aG1[k][0], w11, zA.x); f2fma(aG1[k][1], w11, zA.y);
                f2fma(aG1[k][0], w12, pA.x); f2fma(aG1[k][1], w12, pA.y);

                f2fma(aF0[k][0], w20, aA.x); f2fma(aF0[k][1], w20, aA.y);
                f2fma(aF0[k][0], w21, zA.x); f2fma(aF0[k][1], w21, zA.y);
                f2fma(aF0[k][0], w22, pA.x); f2fma(aF0[k][1], w22, pA.y);

                f2fma(aF1[k][0], w30, aA.x); f2fma(aF1[k][1], w30, aA.y);
                f2fma(aF1[k][0], w31, zA.x); f2fma(aF1[k][1], w31, zA.y);
                f2fma(aF1[k][0], w32, pA.x); f2fma(aF1[k][1], w32, pA.y);
            }
        }

        // ---- LIF (hard reset) + gating, both timesteps in order ----
        float gb0[2][4], gb1[2][4];
#pragma unroll
        for (int k = 0; k < 2; k++){
#pragma unroll
            for (int q = 0; q < 2; q++){
#pragma unroll
                for (int h = 0; h < 2; h++){
                    int idx = 2*q + h;
                    float xg0 = h ? hi32(aG0[k][q]) : lo32(aG0[k][q]);
                    float xg1 = h ? hi32(aG1[k][q]) : lo32(aG1[k][q]);
                    float xf0 = h ? hi32(aF0[k][q]) : lo32(aF0[k][q]);
                    float xf1 = h ? hi32(aF1[k][q]) : lo32(aF1[k][q]);

                    vg0[idx] = vg0[idx] + __fdiv_rn(xg0 - vg0[idx], 1.2f);
                    float s_g0 = (vg0[idx] >= 0.5f) ? 1.f : 0.f;
                    vg0[idx] *= (1.f - s_g0);
                    vg1[idx] = vg1[idx] + __fdiv_rn(xg1 - vg1[idx], 1.2f);
                    float s_g1 = (vg1[idx] >= 0.5f) ? 1.f : 0.f;
                    vg1[idx] *= (1.f - s_g1);
                    vf0[idx] = vf0[idx] + __fdiv_rn(xf0 - vf0[idx], 1.2f);
                    float s_f0 = (vf0[idx] >= 0.5f) ? 1.f : 0.f;
                    vf0[idx] *= (1.f - s_f0);
                    vf1[idx] = vf1[idx] + __fdiv_rn(xf1 - vf1[idx], 1.2f);
                    float s_f1 = (vf1[idx] >= 0.5f) ? 1.f : 0.f;
                    vf1[idx] *= (1.f - s_f1);

                    gb0[k][idx] = ((s_g0 > 0.f) ? SG1 : 0.5f) * ((s_f0 > 0.f) ? TH1 : 0.f);
                    gb1[k][idx] = ((s_g1 > 0.f) ? SG1 : 0.5f) * ((s_f1 > 0.f) ? TH1 : 0.f);
                }
            }
        }
        __syncthreads();   // S2: all conv reads of tile done -> safe to overlay gated

#pragma unroll
        for (int k = 0; k < 2; k++){
            float* g0 = tile + k*12288 + cg*GS_STRIDE;
            float* g1 = tile + k*12288 + (cg+32)*GS_STRIDE;
            *(float4*)(g0 + jA) = make_float4(gb0[k][0], gb0[k][1], gb0[k][2], gb0[k][3]);
            *(float4*)(g1 + jA) = make_float4(gb1[k][0], gb1[k][1], gb1[k][2], gb1[k][3]);
        }
        __syncthreads();   // S3: gated visible

        // ---- skip / res 1x1 convs for both timesteps ----
        unsigned long long sk0[2][2], sk1[2][2], rs0[2][2], rs1[2][2];
#pragma unroll
        for (int k = 0; k < 2; k++)
#pragma unroll
        for (int q = 0; q < 2; q++){ sk0[k][q]=0ull; sk1[k][q]=0ull; rs0[k][q]=0ull; rs1[k][q]=0ull; }

#pragma unroll 4
        for (int ci = 0; ci < Cn; ci++){
            float4 wv = *(const float4*)(wskr + (ci*32 + cg)*4);
            unsigned long long ws0 = pk2(wv.x), ws1 = pk2(wv.y);
            unsigned long long wr0 = pk2(wv.z), wr1 = pk2(wv.w);
#pragma unroll
            for (int k = 0; k < 2; k++){
                const float* grow = tile + k*12288 + ci*GS_STRIDE;
                ulonglong2 gA = *(const ulonglong2*)(grow + jA);
                f2fma(sk0[k][0], ws0, gA.x); f2fma(sk0[k][1], ws0, gA.y);
                f2fma(sk1[k][0], ws1, gA.x); f2fma(sk1[k][1], ws1, gA.y);
                f2fma(rs0[k][0], wr0, gA.x); f2fma(rs0[k][1], wr0, gA.y);
                f2fma(rs1[k][0], wr1, gA.x); f2fma(rs1[k][1], wr1, gA.y);
            }
        }

        // ---- global update for both timesteps, ch cg and cg+32 ----
#pragma unroll
        for (int k = 0; k < 2; k++){
#pragma unroll
            for (int ch = 0; ch < 2; ch++){
                int co = cg + ch*32;
                unsigned long long* skp = ch ? sk1[k] : sk0[k];
                unsigned long long* rsp = ch ? rs1[k] : rs0[k];
                float sbp = ch ? sb1 : sb0;
                float rbp = ch ? rb1 : rb0;
                size_t gbase = ((size_t)((t0+k)*Bn + b)*Cn + co)*Ln + l0;
                float4 sv0 = make_float4(lo32(skp[0])+sbp, hi32(skp[0])+sbp,
                                         lo32(skp[1])+sbp, hi32(skp[1])+sbp);
                float4* skA = (float4*)(g_skip + gbase + jA);
                if (layer != 0){
                    float4 o0 = *skA;
                    sv0.x += o0.x; sv0.y += o0.y; sv0.z += o0.z; sv0.w += o0.w;
                }
                *skA = sv0;

                float4 a0 = *(const float4*)(x_in + gbase + jA);
                a0.x += lo32(rsp[0])+rbp; a0.y += hi32(rsp[0])+rbp;
                a0.z += lo32(rsp[1])+rbp; a0.w += hi32(rsp[1])+rbp;
                *(float4*)(x_out + gbase + jA) = a0;
            }
        }
        __syncthreads();   // S4: 1x1 reads of gated overlay done -> next staging may write tile
    }
}

// ---------------- final: relu(skip) -> 1x1 conv -> LIF -> sum over T ----------------
__global__ void __launch_bounds__(256) out_kernel(const float* __restrict__ wout,
                                                  const float* __restrict__ bout,
                                                  float* __restrict__ out){
    int g = blockIdx.x * 256 + threadIdx.x;     // (b,l)
    int b = g >> 12, l = g & (Ln - 1);
    float bo = bout[0];
    float v = 0.f, ssum = 0.f;
#pragma unroll
    for (int t = 0; t < Tn; t++){
        float acc = bo;
        const float* sk = g_skip + ((size_t)(t*Bn + b))*Cn*Ln + l;
        for (int c = 0; c < Cn; c++){
            float s = sk[(size_t)c*Ln];
            s = (s > 0.f) ? s : 0.f;
            acc += wout[c] * s;
        }
        v = v + __fdiv_rn(acc - v, 1.2f);
        float sp = (v >= 0.5f) ? 1.f : 0.f;
        v *= (1.f - sp);
        ssum += sp;
    }
    out[g] = ssum;
}

// ---------------- launch ----------------
extern "C" void kernel_launch(void* const* d_in, const int* in_sizes, int n_in,
                              void* d_out, int out_size){
    const float* audio   = (const float*)d_in[0];
    const int*   dstep   = (const int*)  d_in[1];
    const float* W_in    = (const float*)d_in[2];
    const float* b_in    = (const float*)d_in[3];
    const float* demb_w1 = (const float*)d_in[4];
    const float* demb_b1 = (const float*)d_in[5];
    const float* demb_w2 = (const float*)d_in[6];
    const float* demb_b2 = (const float*)d_in[7];
    const float* dproj_w = (const float*)d_in[8];
    const float* dproj_b = (const float*)d_in[9];
    const float* conv_w  = (const float*)d_in[10];
    const float* conv_b  = (const float*)d_in[11];
    const float* skip_w  = (const float*)d_in[12];
    const float* skip_b  = (const float*)d_in[13];
    const float* res_w   = (const float*)d_in[14];
    const float* res_b   = (const float*)d_in[15];
    const float* W_out   = (const float*)d_in[16];
    const float* b_out   = (const float*)d_in[17];

    const int SMEM_BYTES = 57664 * 4;   // 230656
    cudaFuncSetAttribute((const void*)layer_kernel,
                         cudaFuncAttributeMaxDynamicSharedMemorySize, SMEM_BYTES);

    enc_kernel<<<(Bn*Ln)/256, 256>>>(audio, W_in, b_in);

    proj_all_kernel<<<NLAYERS, 256>>>(dstep, demb_w1, demb_b1, demb_w2, demb_b2,
                                      dproj_w, dproj_b);

    int flip = 0;
    for (int i = 0; i < NLAYERS; i++){
        layer_kernel<<<dim3(Ln/TL, Bn), LTHREADS, SMEM_BYTES>>>(flip, i,
                                conv_w + i*2*Cn*Cn*3, conv_b + i*2*Cn,
                                skip_w + i*Cn*Cn,     skip_b + i*Cn,
                                res_w  + i*Cn*Cn,     res_b  + i*Cn,
                                1 << i);
        flip ^= 1;
    }

    out_kernel<<<(Bn*Ln)/256, 256>>>(W_out, b_out, (float*)d_out);
}

// round 7
// speedup vs baseline: 3.1266x; 1.0589x over previous
#include <cuda_runtime.h>
#include <math.h>

#define Tn 4
#define Bn 4
#define Cn 64
#define Ln 4096
#define NLAYERS 10
#define TL 64          // l-tile per block
#define LTHREADS 512

// ---------------- scratch (no allocations allowed) ----------------
__device__ float g_xA[Tn*Bn*Cn*Ln];     // 16 MB
__device__ float g_xB[Tn*Bn*Cn*Ln];     // 16 MB
__device__ float g_skip[Tn*Bn*Cn*Ln];   // 16 MB
__device__ float g_proj[NLAYERS*Bn*Cn];

// ---------------- packed f32x2 helpers ----------------
__device__ __forceinline__ unsigned long long pk2(float w){
    unsigned long long r;
    asm("mov.b64 %0, {%1, %1};" : "=l"(r) : "f"(w));
    return r;
}
__device__ __forceinline__ void f2fma(unsigned long long &d, unsigned long long a, unsigned long long b){
    asm("fma.rn.f32x2 %0, %1, %2, %0;" : "+l"(d) : "l"(a), "l"(b));
}
__device__ __forceinline__ float lo32(unsigned long long v){ return __uint_as_float((unsigned)v); }
__device__ __forceinline__ float hi32(unsigned long long v){ return __uint_as_float((unsigned)(v>>32)); }

// ---------------- JAX threefry2x32 (key = (0,42)) ----------------
__device__ __forceinline__ unsigned rotl32(unsigned x, int r){ return (x<<r)|(x>>(32-r)); }

__device__ __forceinline__ void threefry_0_42(unsigned x0, unsigned x1, unsigned &o0, unsigned &o1){
    const unsigned ks0 = 0u, ks1 = 42u, ks2 = 0u ^ 42u ^ 0x1BD11BDAu;
    x0 += ks0; x1 += ks1;
#define TF_RND(r) { x0 += x1; x1 = rotl32(x1,(r)); x1 ^= x0; }
    TF_RND(13) TF_RND(15) TF_RND(26) TF_RND(6)
    x0 += ks1; x1 += ks2 + 1u;
    TF_RND(17) TF_RND(29) TF_RND(16) TF_RND(24)
    x0 += ks2; x1 += ks0 + 2u;
    TF_RND(13) TF_RND(15) TF_RND(26) TF_RND(6)
    x0 += ks0; x1 += ks1 + 3u;
    TF_RND(17) TF_RND(29) TF_RND(16) TF_RND(24)
    x0 += ks1; x1 += ks2 + 4u;
    TF_RND(13) TF_RND(15) TF_RND(26) TF_RND(6)
    x0 += ks2; x1 += ks0 + 5u;
#undef TF_RND
    o0 = x0; o1 = x1;
}
__device__ __forceinline__ float bits2unit(unsigned b){
    return __uint_as_float((b >> 9) | 0x3f800000u) - 1.0f;
}

// ---------------- encoder: poisson + input conv(1x1) + LIF ----------------
__global__ void __launch_bounds__(256) enc_kernel(const float* __restrict__ audio,
                                                  const float* __restrict__ w_in,
                                                  const float* __restrict__ b_in){
    int g = blockIdx.x * 256 + threadIdx.x;      // 0..16383  (b,l)
    int b = g >> 12, l = g & (Ln - 1);
    float a = audio[g];

    unsigned n0 = (unsigned)(b * Ln + l);        // t=0; partner t=2
    unsigned o0, o1, o2, o3;
    threefry_0_42(n0,           n0 + 32768u, o0, o2);
    threefry_0_42(n0 + 16384u,  n0 + 49152u, o1, o3);   // t=1 ; partner t=3

    float sp[4];
    sp[0] = (bits2unit(o0) < a) ? 1.f : 0.f;
    sp[1] = (bits2unit(o1) < a) ? 1.f : 0.f;
    sp[2] = (bits2unit(o2) < a) ? 1.f : 0.f;
    sp[3] = (bits2unit(o3) < a) ? 1.f : 0.f;

    for (int c = 0; c < Cn; c++){
        float w = w_in[c], bi = b_in[c];
        float v = 0.f;
#pragma unroll
        for (int t = 0; t < Tn; t++){
            float x = w * sp[t] + bi;
            v = v + __fdiv_rn(x - v, 1.2f);
            float s = (v >= 0.5f) ? 1.f : 0.f;
            v *= (1.f - s);
            int idx = ((t*Bn + b)*Cn + c)*Ln + l;
            g_xA[idx] = s;
        }
    }
}

// ---------------- ALL layers' diffusion-step embedding + projection ----------------
__global__ void __launch_bounds__(256) proj_all_kernel(const int* __restrict__ dstep,
                                                       const float* __restrict__ w1a,
                                                       const float* __restrict__ b1a,
                                                       const float* __restrict__ w2a,
                                                       const float* __restrict__ b2a,
                                                       const float* __restrict__ dpwa,
                                                       const float* __restrict__ dpba){
    int i = blockIdx.x;   // layer
    const float* w1 = w1a + i*Cn;
    const float* b1 = b1a + i*Cn;
    const float* w2 = w2a + i*Cn*Cn;
    const float* b2 = b2a + i*Cn;
    const float* dpw = dpwa + i*Cn*Cn;
    const float* dpb = dpba + i*Cn;

    __shared__ float h[Bn][Cn];
    __shared__ float e[Bn][Cn];
    int tid = threadIdx.x;
    int b = tid >> 6, c = tid & 63;

    float d = (float)dstep[b];
    float z = d * w1[c] + b1[c];
    float sg = 1.f / (1.f + expf(-z));
    h[b][c] = z * sg;                     // silu
    __syncthreads();

    float acc = b2[c];
    for (int j = 0; j < Cn; j++) acc += h[b][j] * w2[c*Cn + j];
    e[b][c] = acc;
    __syncthreads();

    float p = dpb[c];
    for (int j = 0; j < Cn; j++) p += e[b][j] * dpw[c*Cn + j];
    g_proj[i*Bn*Cn + b*Cn + c] = p;
}

// ---------------- fused layer: 2-timestep dilated conv + LIF + gate + skip/res 1x1 ----
// 512 threads: cg = tid>>4 (couts {cg, cg+32, cg+64, cg+96}); lg = tid&15 -> 4 l each
// raw-x staging via cp.async; proj folded into bias with edge corrections.
__global__ void __launch_bounds__(LTHREADS, 1) layer_kernel(int flip, int layer,
                                                       const float* __restrict__ wconv,
                                                       const float* __restrict__ bconv,
                                                       const float* __restrict__ wskip,
                                                       const float* __restrict__ bskip,
                                                       const float* __restrict__ wres,
                                                       const float* __restrict__ bres,
                                                       int dil){
    const float* x_in  = flip ? g_xB : g_xA;
    float*       x_out = flip ? g_xA : g_xB;

    extern __shared__ float sm[];
    float* wc4  = sm;            // [ci][32 cg][k0:4co, k1:4co, k2:4co]  24576
    float* wskr = wc4  + 24576;  // [ci][32 cg][ws,ws32,wr,wr32]          8192
    float* cb   = wskr + 8192;   // 128
    float* pr   = cb   + 128;    // 64
    float* sbv  = pr   + 64;     // 64
    float* rbv  = sbv  + 64;     // 64
    float* ck   = rbv  + 64;     // [3][128] proj-fold constants          384
    float* tile = ck   + 384;    // 2 timesteps x 3 shifts x [64 ci][64 l] = 24576
                                 // gated overlay (stride 64) reuses s=0 region per timestep
                                 // total = 58048 floats = 232192 B

    const int tid  = threadIdx.x;
    const int b    = blockIdx.y;
    const int l0   = blockIdx.x * TL;
    const int lg   = tid & 15;
    const int cg   = tid >> 4;     // 0..31
    const int jA   = lg * 4;

    // ---- coalesced weight load + scatter repack ----
    for (int i = tid; i < 24576; i += LTHREADS){
        int co = i / 192, r = i % 192, ci = r / 3, k = r % 3;
        int g = co >> 5, cgi = co & 31;
        wc4[((ci*32 + cgi)*3 + k)*4 + g] = wconv[i];
    }
    for (int i = tid; i < 4096; i += LTHREADS){
        int co = i >> 6, ci = i & 63;
        int g = co >> 5, cgi = co & 31;
        wskr[(ci*32 + cgi)*4 + g    ] = wskip[i];
        wskr[(ci*32 + cgi)*4 + g + 2] = wres[i];
    }
    if (tid < 128) cb[tid] = bconv[tid];
    if (tid < 64){
        pr[tid]  = g_proj[layer*Bn*Cn + b*Cn + tid];
        sbv[tid] = bskip[tid];
        rbv[tid] = bres[tid];
    }
    __syncthreads();

    // ---- proj-fold constants: ck[k][cout] = sum_ci wconv[cout,ci,k] * proj[ci] ----
    if (tid < 384){
        int k = tid >> 7;          // 0..2
        int cout = tid & 127;
        int cgi = cout & 31, g = cout >> 5;
        float acc = 0.f;
        for (int ci = 0; ci < Cn; ci++)
            acc += wc4[((ci*32 + cgi)*3 + k)*4 + g] * pr[ci];
        ck[(k << 7) + cout] = acc;
    }
    __syncthreads();

    const float SG1 = 1.f / (1.f + expf(-1.f));
    const float TH1 = tanhf(1.f);

    // folded bias: cb + ck0 + ck1 + ck2
    const unsigned long long cb0 = pk2(cb[cg]    + ck[cg]     + ck[128+cg]     + ck[256+cg]);
    const unsigned long long cb1 = pk2(cb[cg+32] + ck[cg+32]  + ck[128+cg+32]  + ck[256+cg+32]);
    const unsigned long long cb2 = pk2(cb[cg+64] + ck[cg+64]  + ck[128+cg+64]  + ck[256+cg+64]);
    const unsigned long long cb3 = pk2(cb[cg+96] + ck[cg+96]  + ck[128+cg+96]  + ck[256+cg+96]);
    const float sb0 = sbv[cg], sb1 = sbv[cg+32];
    const float rb0 = rbv[cg], rb1 = rbv[cg+32];

    const bool edge = (l0 < dil) || (l0 + TL + dil > Ln);
    float c00=0.f,c01=0.f,c02=0.f,c03=0.f,c20=0.f,c21=0.f,c22=0.f,c23=0.f;
    if (edge){
        c00 = ck[cg];       c01 = ck[cg+32];       c02 = ck[cg+64];       c03 = ck[cg+96];
        c20 = ck[256+cg];   c21 = ck[256+cg+32];   c22 = ck[256+cg+64];   c23 = ck[256+cg+96];
    }

    // LIF membrane: 4 couts x 4 l (persist across tt iterations)
    float vg0[4], vg1[4], vf0[4], vf1[4];
#pragma unroll
    for (int k = 0; k < 4; k++){ vg0[k]=0.f; vg1[k]=0.f; vf0[k]=0.f; vf1[k]=0.f; }

    for (int tt = 0; tt < 2; tt++){
        const int t0 = tt * 2;

        // ---- stage raw x tiles, zero-padded: cp.async path for dil>=4 ----
        if (dil >= 4){
#pragma unroll
            for (int k = 0; k < 2; k++){
                const float* xk = x_in + ((size_t)((t0+k)*Bn + b)) * Cn * Ln;
#pragma unroll
                for (int s = 0; s < 3; s++){
                    int off = l0 + (s - 1) * dil;
#pragma unroll
                    for (int w = 0; w < 2; w++){
                        int q  = tid + w*LTHREADS;   // 0..1023
                        int ci = q >> 4;
                        int jc = (q & 15) << 2;
                        int gl = off + jc;
                        unsigned ss = ((unsigned)gl <= 4092u) ? 16u : 0u;
                        const float* src = ss ? (xk + ci*Ln + gl) : xk;
                        unsigned daddr = (unsigned)__cvta_generic_to_shared(
                                             tile + k*12288 + s*4096 + (ci<<6) + jc);
                        asm volatile("cp.async.ca.shared.global [%0], [%1], 16, %2;"
                                     :: "r"(daddr), "l"(src), "r"(ss) : "memory");
                    }
                }
            }
            asm volatile("cp.async.commit_group;" ::: "memory");
            asm volatile("cp.async.wait_group 0;" ::: "memory");
        } else {
            // scalar path (dil = 1 or 2): raw x, zero-padded
#pragma unroll
            for (int k = 0; k < 2; k++){
                const float* xk = x_in + ((size_t)((t0+k)*Bn + b)) * Cn * Ln;
                float* tk = tile + k*12288;
#pragma unroll 4
                for (int i = tid; i < 3*Cn*TL; i += LTHREADS){
                    int s  = i >> 12;
                    int r  = i & 4095;
                    int ci = r >> 6; int j = r & 63;
                    int gl = l0 + j + (s - 1) * dil;
                    float val = 0.f;
                    if ((unsigned)gl < (unsigned)Ln) val = xk[ci*Ln + gl];
                    tk[i] = val;
                }
            }
        }
        __syncthreads();   // S1: tiles ready

        // ---- dilated conv, 4 couts x 4 l x 2 timesteps per thread ----
        unsigned long long aG0[2][2], aG1[2][2], aF0[2][2], aF1[2][2];
#pragma unroll
        for (int k = 0; k < 2; k++)
#pragma unroll
        for (int q = 0; q < 2; q++){ aG0[k][q]=cb0; aG1[k][q]=cb1; aF0[k][q]=cb2; aF1[k][q]=cb3; }

#pragma unroll 2
        for (int ci = 0; ci < Cn; ci++){
            const float* wrow = wc4 + (ci*32 + cg)*12;
            float4 k0 = *(const float4*)(wrow);
            float4 k1 = *(const float4*)(wrow + 4);
            float4 k2 = *(const float4*)(wrow + 8);
            unsigned long long w00=pk2(k0.x), w01=pk2(k1.x), w02=pk2(k2.x);
            unsigned long long w10=pk2(k0.y), w11=pk2(k1.y), w12=pk2(k2.y);
            unsigned long long w20=pk2(k0.z), w21=pk2(k1.z), w22=pk2(k2.z);
            unsigned long long w30=pk2(k0.w), w31=pk2(k1.w), w32=pk2(k2.w);
#pragma unroll
            for (int k = 0; k < 2; k++){
                const float* trow = tile + k*12288 + (ci << 6);
                ulonglong2 aA = *(const ulonglong2*)(trow + jA);
                ulonglong2 zA = *(const ulonglong2*)(trow + 4096 + jA);
                ulonglong2 pA = *(const ulonglong2*)(trow + 8192 + jA);
                f2fma(aG0[k][0], w00, aA.x); f2fma(aG0[k][1], w00, aA.y);
                f2fma(aG0[k][0], w01, zA.x); f2fma(aG0[k][1], w01, zA.y);
                f2fma(aG0[k][0], w02, pA.x); f2fma(aG0[k][1], w02, pA.y);

                f2fma(aG1[k][0], w10, aA.x); f2fma(aG1[k][1], w10, aA.y);
                f2fma(aG1[k][0], w11, zA.x); f2fma(aG1[k][1], w11, zA.y);
                f2fma(aG1[k][0], w12, pA.x); f2fma(aG1[k][1], w12, pA.y);

                f2fma(aF0[k][0], w20, aA.x); f2fma(aF0[k][1], w20, aA.y);
                f2fma(aF0[k][0], w21, zA.x); f2fma(aF0[k][1], w21, zA.y);
                f2fma(aF0[k][0], w22, pA.x); f2fma(aF0[k][1], w22, pA.y);

                f2fma(aF1[k][0], w30, aA.x); f2fma(aF1[k][1], w30, aA.y);
                f2fma(aF1[k][0], w31, zA.x); f2fma(aF1[k][1], w31, zA.y);
                f2fma(aF1[k][0], w32, pA.x); f2fma(aF1[k][1], w32, pA.y);
            }
        }

        // ---- LIF (hard reset) + gating, both timesteps in order ----
        float gb0[2][4], gb1[2][4];
#pragma unroll
        for (int k = 0; k < 2; k++){
#pragma unroll
            for (int q = 0; q < 2; q++){
#pragma unroll
                for (int h = 0; h < 2; h++){
                    int idx = 2*q + h;
                    float xg0 = h ? hi32(aG0[k][q]) : lo32(aG0[k][q]);
                    float xg1 = h ? hi32(aG1[k][q]) : lo32(aG1[k][q]);
                    float xf0 = h ? hi32(aF0[k][q]) : lo32(aF0[k][q]);
                    float xf1 = h ? hi32(aF1[k][q]) : lo32(aF1[k][q]);

                    if (edge){
                        int gl = l0 + jA + idx;
                        float f0 = (gl < dil) ? 1.f : 0.f;
                        float f2 = (gl >= Ln - dil) ? 1.f : 0.f;
                        xg0 -= f0*c00 + f2*c20;
                        xg1 -= f0*c01 + f2*c21;
                        xf0 -= f0*c02 + f2*c22;
                        xf1 -= f0*c03 + f2*c23;
                    }

                    vg0[idx] = vg0[idx] + __fdiv_rn(xg0 - vg0[idx], 1.2f);
                    float s_g0 = (vg0[idx] >= 0.5f) ? 1.f : 0.f;
                    vg0[idx] *= (1.f - s_g0);
                    vg1[idx] = vg1[idx] + __fdiv_rn(xg1 - vg1[idx], 1.2f);
                    float s_g1 = (vg1[idx] >= 0.5f) ? 1.f : 0.f;
                    vg1[idx] *= (1.f - s_g1);
                    vf0[idx] = vf0[idx] + __fdiv_rn(xf0 - vf0[idx], 1.2f);
                    float s_f0 = (vf0[idx] >= 0.5f) ? 1.f : 0.f;
                    vf0[idx] *= (1.f - s_f0);
                    vf1[idx] = vf1[idx] + __fdiv_rn(xf1 - vf1[idx], 1.2f);
                    float s_f1 = (vf1[idx] >= 0.5f) ? 1.f : 0.f;
                    vf1[idx] *= (1.f - s_f1);

                    gb0[k][idx] = ((s_g0 > 0.f) ? SG1 : 0.5f) * ((s_f0 > 0.f) ? TH1 : 0.f);
                    gb1[k][idx] = ((s_g1 > 0.f) ? SG1 : 0.5f) * ((s_f1 > 0.f) ? TH1 : 0.f);
                }
            }
        }
        __syncthreads();   // S2: conv reads of tile done -> safe to overlay gated into s=0 region

#pragma unroll
        for (int k = 0; k < 2; k++){
            float* g0 = tile + k*12288 + (cg << 6);
            float* g1 = tile + k*12288 + ((cg+32) << 6);
            *(float4*)(g0 + jA) = make_float4(gb0[k][0], gb0[k][1], gb0[k][2], gb0[k][3]);
            *(float4*)(g1 + jA) = make_float4(gb1[k][0], gb1[k][1], gb1[k][2], gb1[k][3]);
        }
        __syncthreads();   // S3: gated visible

        // ---- skip / res 1x1 convs for both timesteps (gated in s=0 overlay) ----
        unsigned long long sk0[2][2], sk1[2][2], rs0[2][2], rs1[2][2];
#pragma unroll
        for (int k = 0; k < 2; k++)
#pragma unroll
        for (int q = 0; q < 2; q++){ sk0[k][q]=0ull; sk1[k][q]=0ull; rs0[k][q]=0ull; rs1[k][q]=0ull; }

#pragma unroll 4
        for (int ci = 0; ci < Cn; ci++){
            float4 wv = *(const float4*)(wskr + (ci*32 + cg)*4);
            unsigned long long ws0 = pk2(wv.x), ws1 = pk2(wv.y);
            unsigned long long wr0 = pk2(wv.z), wr1 = pk2(wv.w);
#pragma unroll
            for (int k = 0; k < 2; k++){
                const float* grow = tile + k*12288 + (ci << 6);
                ulonglong2 gA = *(const ulonglong2*)(grow + jA);
                f2fma(sk0[k][0], ws0, gA.x); f2fma(sk0[k][1], ws0, gA.y);
                f2fma(sk1[k][0], ws1, gA.x); f2fma(sk1[k][1], ws1, gA.y);
                f2fma(rs0[k][0], wr0, gA.x); f2fma(rs0[k][1], wr0, gA.y);
                f2fma(rs1[k][0], wr1, gA.x); f2fma(rs1[k][1], wr1, gA.y);
            }
        }

        // ---- global update: skip RMW; x_out = x(center tap smem) + res ----
#pragma unroll
        for (int k = 0; k < 2; k++){
#pragma unroll
            for (int ch = 0; ch < 2; ch++){
                int co = cg + ch*32;
                unsigned long long* skp = ch ? sk1[k] : sk0[k];
                unsigned long long* rsp = ch ? rs1[k] : rs0[k];
                float sbp = ch ? sb1 : sb0;
                float rbp = ch ? rb1 : rb0;
                size_t gbase = ((size_t)((t0+k)*Bn + b)*Cn + co)*Ln + l0;
                float4 sv0 = make_float4(lo32(skp[0])+sbp, hi32(skp[0])+sbp,
                                         lo32(skp[1])+sbp, hi32(skp[1])+sbp);
                float4* skA = (float4*)(g_skip + gbase + jA);
                if (layer != 0){
                    float4 o0 = *skA;
                    sv0.x += o0.x; sv0.y += o0.y; sv0.z += o0.z; sv0.w += o0.w;
                }
                *skA = sv0;

                if (layer != NLAYERS-1){
                    // raw x center tap lives in smem (s=1 region untouched by overlay)
                    float4 a0 = *(const float4*)(tile + k*12288 + 4096 + (co << 6) + jA);
                    a0.x += lo32(rsp[0])+rbp; a0.y += hi32(rsp[0])+rbp;
                    a0.z += lo32(rsp[1])+rbp; a0.w += hi32(rsp[1])+rbp;
                    *(float4*)(x_out + gbase + jA) = a0;
                }
            }
        }
        __syncthreads();   // S4: overlay reads done -> next staging may write tile
    }
}

// ---------------- final: relu(skip) -> 1x1 conv -> LIF -> sum over T ----------------
__global__ void __launch_bounds__(256) out_kernel(const float* __restrict__ wout,
                                                  const float* __restrict__ bout,
                                                  float* __restrict__ out){
    int g = blockIdx.x * 256 + threadIdx.x;     // (b,l)
    int b = g >> 12, l = g & (Ln - 1);
    float bo = bout[0];
    float v = 0.f, ssum = 0.f;
#pragma unroll
    for (int t = 0; t < Tn; t++){
        float acc = bo;
        const float* sk = g_skip + ((size_t)(t*Bn + b))*Cn*Ln + l;
        for (int c = 0; c < Cn; c++){
            float s = sk[(size_t)c*Ln];
            s = (s > 0.f) ? s : 0.f;
            acc += wout[c] * s;
        }
        v = v + __fdiv_rn(acc - v, 1.2f);
        float sp = (v >= 0.5f) ? 1.f : 0.f;
        v *= (1.f - sp);
        ssum += sp;
    }
    out[g] = ssum;
}

// ---------------- launch ----------------
extern "C" void kernel_launch(void* const* d_in, const int* in_sizes, int n_in,
                              void* d_out, int out_size){
    const float* audio   = (const float*)d_in[0];
    const int*   dstep   = (const int*)  d_in[1];
    const float* W_in    = (const float*)d_in[2];
    const float* b_in    = (const float*)d_in[3];
    const float* demb_w1 = (const float*)d_in[4];
    const float* demb_b1 = (const float*)d_in[5];
    const float* demb_w2 = (const float*)d_in[6];
    const float* demb_b2 = (const float*)d_in[7];
    const float* dproj_w = (const float*)d_in[8];
    const float* dproj_b = (const float*)d_in[9];
    const float* conv_w  = (const float*)d_in[10];
    const float* conv_b  = (const float*)d_in[11];
    const float* skip_w  = (const float*)d_in[12];
    const float* skip_b  = (const float*)d_in[13];
    const float* res_w   = (const float*)d_in[14];
    const float* res_b   = (const float*)d_in[15];
    const float* W_out   = (const float*)d_in[16];
    const float* b_out   = (const float*)d_in[17];

    const int SMEM_BYTES = 58048 * 4;   // 232192
    cudaFuncSetAttribute((const void*)layer_kernel,
                         cudaFuncAttributeMaxDynamicSharedMemorySize, SMEM_BYTES);

    enc_kernel<<<(Bn*Ln)/256, 256>>>(audio, W_in, b_in);

    proj_all_kernel<<<NLAYERS, 256>>>(dstep, demb_w1, demb_b1, demb_w2, demb_b2,
                                      dproj_w, dproj_b);

    int flip = 0;
    for (int i = 0; i < NLAYERS; i++){
        layer_kernel<<<dim3(Ln/TL, Bn), LTHREADS, SMEM_BYTES>>>(flip, i,
                                conv_w + i*2*Cn*Cn*3, conv_b + i*2*Cn,
                                skip_w + i*Cn*Cn,     skip_b + i*Cn,
                                res_w  + i*Cn*Cn,     res_b  + i*Cn,
                                1 << i);
        flip ^= 1;
    }

    out_kernel<<<(Bn*Ln)/256, 256>>>(W_out, b_out, (float*)d_out);
}